// round 6
// baseline (speedup 1.0000x reference)
#include <cuda_runtime.h>

#define NB 8
#define NT 2048
#define ND 1024
#define NH 64
#define SPL 2

typedef unsigned long long ull;

__device__ __forceinline__ ull pack2s(float v) {
    ull r; asm("mov.b64 %0, {%1, %2};" : "=l"(r) : "f"(v), "f"(v)); return r;
}
__device__ __forceinline__ void fma2(ull& d, ull a, ull b) {
    asm("fma.rn.f32x2 %0, %1, %2, %0;" : "+l"(d) : "l"(a), "l"(b));
}
__device__ __forceinline__ void mul2(ull& d, ull a) {
    asm("mul.rn.f32x2 %0, %0, %1;" : "+l"(d) : "l"(a));
}
__device__ __forceinline__ float2 unpack2(ull v) {
    float2 r; asm("mov.b64 {%0, %1}, %2;" : "=f"(r.x), "=f"(r.y) : "l"(v)); return r;
}

// Q,K transposed [b][h][t]; V row-major [b][t][h]; split-K partials.
__device__ float g_qT[NB * NH * NT];
__device__ float g_kT[NB * NH * NT];
__device__ float g_v [NB * NT * NH];
__device__ float g_po[(size_t)NB * NT * SPL * NH];
__device__ float g_pm[NB * NT * SPL];
__device__ float g_pl[NB * NT * SPL];

// key -> permuted word offset inside a duplicated 132-word row:
// offset(k) = 32*(k&3) + 2*(k>>2)   (conflict-free for kg-strided access)
__device__ __forceinline__ int kperm(int k) { return 32 * (k & 3) + 2 * (k >> 2); }

// ---------------------------------------------------------------------------
// Projection: 64x64 tile of matrix z per block. 128 threads, 4 rows x 8 cols
// per thread, col-paired f32x2 accs. x duplicated (broadcast pairs) in smem.
// ---------------------------------------------------------------------------
__global__ __launch_bounds__(128) void proj_kernel(
    const float* __restrict__ x, const float* __restrict__ Wq,
    const float* __restrict__ Wk, const float* __restrict__ Wv,
    const int* __restrict__ valid_lens)
{
    const int b  = blockIdx.y;
    const int t0 = blockIdx.x * 64;
    const int z  = blockIdx.z;
    int L = valid_lens[b];
    if (L < 0) L = 0;
    if (L > NT) L = NT;
    if (t0 >= L) return;

    const float* __restrict__ W = (z == 0) ? Wq : ((z == 1) ? Wk : Wv);

    __shared__ __align__(16) float xsD[2][16][132];  // [buf][k][2*row dup]
    __shared__ __align__(16) float ws [2][16][72];   // [buf][k][col]

    const int tid = threadIdx.x;
    const int tx  = tid & 7;    // col group *8
    const int ty  = tid >> 3;   // row group *4 (0..15)

    const int xr  = tid >> 2;          // 0..31 (+32)
    const int xk4 = (tid & 3) * 4;
    const int wk  = tid >> 4;          // 0..7 (+8)
    const int wc4 = (tid & 15) * 4;

    ull acc[4][4];
    #pragma unroll
    for (int i = 0; i < 4; i++)
        #pragma unroll
        for (int j = 0; j < 4; j++) acc[i][j] = 0ull;

    // preload kb=0 into buf 0
    {
        #pragma unroll
        for (int i = 0; i < 2; i++) {
            int r = xr + 32 * i;
            float4 v = *(const float4*)&x[((size_t)b * NT + t0 + r) * ND + xk4];
            *(float2*)&xsD[0][xk4 + 0][2 * r] = make_float2(v.x, v.x);
            *(float2*)&xsD[0][xk4 + 1][2 * r] = make_float2(v.y, v.y);
            *(float2*)&xsD[0][xk4 + 2][2 * r] = make_float2(v.z, v.z);
            *(float2*)&xsD[0][xk4 + 3][2 * r] = make_float2(v.w, v.w);
        }
        #pragma unroll
        for (int i = 0; i < 2; i++) {
            int k = wk + 8 * i;
            *(float4*)&ws[0][k][wc4] = *(const float4*)&W[(size_t)k * NH + wc4];
        }
    }
    __syncthreads();

    int buf = 0;
    for (int kb = 0; kb < ND; kb += 16) {
        if (kb + 16 < ND) {
            const int nb = buf ^ 1;
            #pragma unroll
            for (int i = 0; i < 2; i++) {
                int r = xr + 32 * i;
                float4 v = *(const float4*)&x[((size_t)b * NT + t0 + r) * ND + kb + 16 + xk4];
                *(float2*)&xsD[nb][xk4 + 0][2 * r] = make_float2(v.x, v.x);
                *(float2*)&xsD[nb][xk4 + 1][2 * r] = make_float2(v.y, v.y);
                *(float2*)&xsD[nb][xk4 + 2][2 * r] = make_float2(v.z, v.z);
                *(float2*)&xsD[nb][xk4 + 3][2 * r] = make_float2(v.w, v.w);
            }
            #pragma unroll
            for (int i = 0; i < 2; i++) {
                int k = wk + 8 * i;
                *(float4*)&ws[nb][k][wc4] =
                    *(const float4*)&W[(size_t)(kb + 16 + k) * NH + wc4];
            }
        }
        #pragma unroll
        for (int kk = 0; kk < 16; kk++) {
            ull a0 = *(const ull*)&xsD[buf][kk][2 * (ty * 4 + 0)];
            ull a1 = *(const ull*)&xsD[buf][kk][2 * (ty * 4 + 1)];
            ull a2 = *(const ull*)&xsD[buf][kk][2 * (ty * 4 + 2)];
            ull a3 = *(const ull*)&xsD[buf][kk][2 * (ty * 4 + 3)];
            ulonglong2 w01 = *(const ulonglong2*)&ws[buf][kk][tx * 8];
            ulonglong2 w23 = *(const ulonglong2*)&ws[buf][kk][tx * 8 + 4];
            ull wc[4] = { w01.x, w01.y, w23.x, w23.y };
            ull ar[4] = { a0, a1, a2, a3 };
            #pragma unroll
            for (int i = 0; i < 4; i++)
                #pragma unroll
                for (int j = 0; j < 4; j++)
                    fma2(acc[i][j], ar[i], wc[j]);
        }
        __syncthreads();
        buf ^= 1;
    }

    if (z < 2) {  // transposed store OT[b][col][t]
        float* __restrict__ OT = (z == 0) ? g_qT : g_kT;
        #pragma unroll
        for (int j = 0; j < 4; j++) {
            float2 u0 = unpack2(acc[0][j]), u1 = unpack2(acc[1][j]);
            float2 u2 = unpack2(acc[2][j]), u3 = unpack2(acc[3][j]);
            const int c0 = tx * 8 + 2 * j;
            const size_t b0 = (size_t)(b * NH + c0) * NT + t0 + ty * 4;
            *(float4*)&OT[b0]      = make_float4(u0.x, u1.x, u2.x, u3.x);
            *(float4*)&OT[b0 + NT] = make_float4(u0.y, u1.y, u2.y, u3.y);
        }
    } else {      // V row-major: cols contiguous per row
        #pragma unroll
        for (int i = 0; i < 4; i++) {
            const size_t r0 = ((size_t)b * NT + t0 + ty * 4 + i) * NH + tx * 8;
            ulonglong2 s0; s0.x = acc[i][0]; s0.y = acc[i][1];
            ulonglong2 s1; s1.x = acc[i][2]; s1.y = acc[i][3];
            *(ulonglong2*)&g_v[r0]     = s0;
            *(ulonglong2*)&g_v[r0 + 4] = s1;
        }
    }
}

// ---------------------------------------------------------------------------
// Flash-attention partials: BQ=64, BK=64, 128 threads, split-K via z.
// S: row-paired accs (Q pairs natural, K duplicated+permuted).
// PV: h-paired accs (V pairs natural, P duplicated+permuted).
// ---------------------------------------------------------------------------
#define OFF_QT 0                       // QsT [64h][72r]
#define OFF_KD (64 * 72)               // KsD [64h][132]
#define OFF_VS (OFF_KD + 64 * 132)     // Vs  [64k][68h]
#define OFF_PD (OFF_VS + 64 * 68)      // PsD [64r][132]
#define OFF_CR (OFF_PD + 64 * 132)     // corr[64]
#define SM_FLOATS (OFF_CR + 64)
#define SM_BYTES (SM_FLOATS * 4)

__global__ __launch_bounds__(128) void attn_part(const int* __restrict__ valid_lens)
{
    extern __shared__ float sm[];
    const int b  = blockIdx.y;
    const int q0 = blockIdx.x * 64;
    const int s  = blockIdx.z;
    int L = valid_lens[b];
    if (L < 0) L = 0;
    if (L > NT) L = NT;
    if (q0 >= L) return;

    const int tid = threadIdx.x;
    const int kg  = tid & 15;     // S: 16 key groups *4
    const int rg  = tid >> 4;     // 8 row groups *8 (S and PV)
    const int hgp = tid & 15;     // PV: 16 h groups *4

    const int kend = (q0 + 64 < L) ? (q0 + 64) : L;
    const int C  = (((kend + SPL - 1) / SPL) + 63) & ~63;
    const int jb = s * C;
    const int je = (jb + C < kend) ? (jb + C) : kend;

    if (jb >= je) {
        const float4 z4 = make_float4(0.f, 0.f, 0.f, 0.f);
        #pragma unroll
        for (int i = 0; i < 8; i++) {
            int idx = tid + 128 * i;
            int row = idx >> 4, h4 = (idx & 15) * 4;
            *(float4*)&g_po[((size_t)(b * NT + q0 + row) * SPL + s) * NH + h4] = z4;
        }
        if (tid < 64) {
            g_pm[(size_t)(b * NT + q0 + tid) * SPL + s] = -1e30f;
            g_pl[(size_t)(b * NT + q0 + tid) * SPL + s] = 0.f;
        }
        return;
    }

    // QsT load (once)
    #pragma unroll
    for (int i = 0; i < 8; i++) {
        int idx = tid + 128 * i;
        int h = idx >> 4, r4 = (idx & 15) * 4;
        *(float4*)&sm[OFF_QT + h * 72 + r4] =
            *(const float4*)&g_qT[(size_t)(b * NH + h) * NT + q0 + r4];
    }

    float m[8], l[8];
    #pragma unroll
    for (int i = 0; i < 8; i++) { m[i] = -1e30f; l[i] = 0.f; }
    ull o[8][2];
    #pragma unroll
    for (int i = 0; i < 8; i++) { o[i][0] = 0ull; o[i][1] = 0ull; }

    for (int j0 = jb; j0 < je; j0 += 64) {
        __syncthreads();
        // KsD: duplicated+permuted; Vs: natural
        #pragma unroll
        for (int i = 0; i < 8; i++) {
            int idx = tid + 128 * i;
            int h = idx >> 4, k4 = (idx & 15) * 4;
            float4 kv = *(const float4*)&g_kT[(size_t)(b * NH + h) * NT + j0 + k4];
            *(float2*)&sm[OFF_KD + h * 132 + kperm(k4 + 0)] = make_float2(kv.x, kv.x);
            *(float2*)&sm[OFF_KD + h * 132 + kperm(k4 + 1)] = make_float2(kv.y, kv.y);
            *(float2*)&sm[OFF_KD + h * 132 + kperm(k4 + 2)] = make_float2(kv.z, kv.z);
            *(float2*)&sm[OFF_KD + h * 132 + kperm(k4 + 3)] = make_float2(kv.w, kv.w);
            int key = idx >> 4, h4 = (idx & 15) * 4;
            *(float4*)&sm[OFF_VS + key * 68 + h4] =
                *(const float4*)&g_v[((size_t)b * NT + j0 + key) * NH + h4];
        }
        __syncthreads();

        // ---- S = Q K^T : sacc[p][j] = row-pair p (rows 2p,2p+1), key kg*4+j
        ull sacc[4][4];
        #pragma unroll
        for (int p = 0; p < 4; p++)
            #pragma unroll
            for (int j = 0; j < 4; j++) sacc[p][j] = 0ull;

        #pragma unroll 8
        for (int h = 0; h < NH; h++) {
            ulonglong2 qa = *(const ulonglong2*)&sm[OFF_QT + h * 72 + rg * 8];
            ulonglong2 qb = *(const ulonglong2*)&sm[OFF_QT + h * 72 + rg * 8 + 4];
            ull qp[4] = { qa.x, qa.y, qb.x, qb.y };
            ull kd[4];
            #pragma unroll
            for (int j = 0; j < 4; j++)
                kd[j] = *(const ull*)&sm[OFF_KD + h * 132 + 32 * j + 2 * kg];
            #pragma unroll
            for (int p = 0; p < 4; p++)
                #pragma unroll
                for (int j = 0; j < 4; j++)
                    fma2(sacc[p][j], qp[p], kd[j]);
        }
        // word 32*j + 2*kg holds key 4*kg + j (kperm inverse mapping)

        // ---- softmax per row, write PsD duplicated+permuted
        #pragma unroll
        for (int p = 0; p < 4; p++) {
            float2 u[4];
            #pragma unroll
            for (int j = 0; j < 4; j++) u[j] = unpack2(sacc[p][j]);
            #pragma unroll
            for (int half = 0; half < 2; half++) {
                const int i  = 2 * p + half;
                const int q  = q0 + rg * 8 + i;
                float sv[4];
                #pragma unroll
                for (int j = 0; j < 4; j++) sv[j] = half ? u[j].y : u[j].x;
                #pragma unroll
                for (int j = 0; j < 4; j++) {
                    int key = j0 + kg * 4 + j;
                    bool valid = (key <= q) && (key < L);
                    sv[j] = valid ? sv[j] * 0.125f : -1e30f;
                }
                float tm = fmaxf(fmaxf(sv[0], sv[1]), fmaxf(sv[2], sv[3]));
                #pragma unroll
                for (int off = 1; off < 16; off <<= 1)
                    tm = fmaxf(tm, __shfl_xor_sync(0xffffffffu, tm, off));
                const float mn = fmaxf(m[i], tm);
                const float corr = __expf(m[i] - mn);
                float pj[4], psum = 0.f;
                #pragma unroll
                for (int j = 0; j < 4; j++) {
                    pj[j] = (sv[j] > -1e29f) ? __expf(sv[j] - mn) : 0.f;
                    psum += pj[j];
                }
                #pragma unroll
                for (int off = 1; off < 16; off <<= 1)
                    psum += __shfl_xor_sync(0xffffffffu, psum, off);
                l[i] = l[i] * corr + psum;
                m[i] = mn;
                const int rbase = OFF_PD + (rg * 8 + i) * 132;
                #pragma unroll
                for (int j = 0; j < 4; j++)
                    *(float2*)&sm[rbase + 32 * j + 2 * kg] = make_float2(pj[j], pj[j]);
                if (kg == 0) sm[OFF_CR + rg * 8 + i] = corr;
            }
        }
        __syncthreads();

        // ---- rescale O, then O += P V
        #pragma unroll
        for (int i = 0; i < 8; i++) {
            ull c2 = pack2s(sm[OFF_CR + rg * 8 + i]);
            mul2(o[i][0], c2);
            mul2(o[i][1], c2);
        }
        #pragma unroll 2
        for (int k = 0; k < 64; k++) {
            ulonglong2 vv = *(const ulonglong2*)&sm[OFF_VS + k * 68 + hgp * 4];
            const int ko = kperm(k);
            #pragma unroll
            for (int i = 0; i < 8; i++) {
                ull pp = *(const ull*)&sm[OFF_PD + (rg * 8 + i) * 132 + ko];
                fma2(o[i][0], pp, vv.x);
                fma2(o[i][1], pp, vv.y);
            }
        }
    }

    // write pm/pl
    if (kg == 0) {
        #pragma unroll
        for (int i = 0; i < 8; i++) {
            const size_t pi = (size_t)(b * NT + q0 + rg * 8 + i) * SPL + s;
            g_pm[pi] = m[i];
            g_pl[pi] = l[i];
        }
    }
    // write po
    #pragma unroll
    for (int i = 0; i < 8; i++) {
        float2 a = unpack2(o[i][0]), c = unpack2(o[i][1]);
        const size_t po = ((size_t)(b * NT + q0 + rg * 8 + i) * SPL + s) * NH + hgp * 4;
        *(float4*)&g_po[po] = make_float4(a.x, a.y, c.x, c.y);
    }
}

// ---------------------------------------------------------------------------
// Combine split-K partials.
// ---------------------------------------------------------------------------
__global__ __launch_bounds__(128) void attn_combine(
    const int* __restrict__ valid_lens, float* __restrict__ out)
{
    const int b   = blockIdx.y;
    const int tid = threadIdx.x;
    const int row = tid >> 3;
    const int t8  = tid & 7;
    const int q   = blockIdx.x * 16 + row;
    int L = valid_lens[b];
    if (L < 0) L = 0;
    if (L > NT) L = NT;

    const size_t base0 = (size_t)(b * NT + q) * SPL;
    float ms[SPL], mstar = -1e30f;
    #pragma unroll
    for (int s = 0; s < SPL; s++) {
        ms[s] = g_pm[base0 + s];
        mstar = fmaxf(mstar, ms[s]);
    }
    float l = 0.f;
    float4 oA = make_float4(0.f, 0.f, 0.f, 0.f);
    float4 oB = make_float4(0.f, 0.f, 0.f, 0.f);
    #pragma unroll
    for (int s = 0; s < SPL; s++) {
        const float w = (ms[s] > -1e29f) ? __expf(ms[s] - mstar) : 0.f;
        l += g_pl[base0 + s] * w;
        float4 a = *(const float4*)&g_po[(base0 + s) * NH + t8 * 4];
        float4 c = *(const float4*)&g_po[(base0 + s) * NH + 32 + t8 * 4];
        oA.x += a.x * w; oA.y += a.y * w; oA.z += a.z * w; oA.w += a.w * w;
        oB.x += c.x * w; oB.y += c.y * w; oB.z += c.z * w; oB.w += c.w * w;
    }
    const float inv = (q < L && l > 0.f) ? (1.f / l) : 0.f;
    const size_t ob = ((size_t)b * NT + q) * NH;
    *(float4*)&out[ob + t8 * 4] =
        make_float4(oA.x * inv, oA.y * inv, oA.z * inv, oA.w * inv);
    *(float4*)&out[ob + 32 + t8 * 4] =
        make_float4(oB.x * inv, oB.y * inv, oB.z * inv, oB.w * inv);
}

extern "C" void kernel_launch(void* const* d_in, const int* in_sizes, int n_in,
                              void* d_out, int out_size)
{
    const float* x  = (const float*)d_in[0];
    const float* Wq = (const float*)d_in[1];
    const float* Wk = (const float*)d_in[2];
    const float* Wv = (const float*)d_in[3];
    const int*   vl = (const int*)d_in[4];
    float* out = (float*)d_out;

    cudaFuncSetAttribute(attn_part, cudaFuncAttributeMaxDynamicSharedMemorySize, SM_BYTES);

    proj_kernel<<<dim3(NT / 64, NB, 3), 128>>>(x, Wq, Wk, Wv, vl);
    attn_part<<<dim3(NT / 64, NB, SPL), 128, SM_BYTES>>>(vl);
    attn_combine<<<dim3(NT / 16, NB), 128>>>(vl, out);
}

// round 7
// speedup vs baseline: 1.2393x; 1.2393x over previous
#include <cuda_runtime.h>

#define NB 8
#define NT 2048
#define ND 1024
#define NH 64
#define SPL 2

typedef unsigned long long ull;

__device__ __forceinline__ ull pack2s(float v) {
    ull r; asm("mov.b64 %0, {%1, %2};" : "=l"(r) : "f"(v), "f"(v)); return r;
}
__device__ __forceinline__ void fma2(ull& d, ull a, ull b) {
    asm("fma.rn.f32x2 %0, %1, %2, %0;" : "+l"(d) : "l"(a), "l"(b));
}
__device__ __forceinline__ void mul2(ull& d, ull a) {
    asm("mul.rn.f32x2 %0, %0, %1;" : "+l"(d) : "l"(a));
}
__device__ __forceinline__ float2 unpack2(ull v) {
    float2 r; asm("mov.b64 {%0, %1}, %2;" : "=f"(r.x), "=f"(r.y) : "l"(v)); return r;
}

// Q,K transposed [b][h][t]; V row-major [b][t][h]; split-K partials.
__device__ float g_qT[NB * NH * NT];
__device__ float g_kT[NB * NH * NT];
__device__ float g_v [NB * NT * NH];
__device__ float g_po[(size_t)NB * NT * SPL * NH];
__device__ float g_pm[NB * NT * SPL];
__device__ float g_pl[NB * NT * SPL];

// ---------------------------------------------------------------------------
// Projection: 64x64 tile of matrix z per block. 256 threads, 4x4 per thread
// (col-paired f32x2 accs), BK=32, double-buffered smem (1 barrier / chunk).
// ---------------------------------------------------------------------------
__global__ __launch_bounds__(256) void proj_kernel(
    const float* __restrict__ x, const float* __restrict__ Wq,
    const float* __restrict__ Wk, const float* __restrict__ Wv,
    const int* __restrict__ valid_lens)
{
    const int b  = blockIdx.y;
    const int t0 = blockIdx.x * 64;
    const int z  = blockIdx.z;
    int L = valid_lens[b];
    if (L < 0) L = 0;
    if (L > NT) L = NT;
    if (t0 >= L) return;

    const float* __restrict__ W = (z == 0) ? Wq : ((z == 1) ? Wk : Wv);

    __shared__ __align__(16) float xs[2][32][68];  // [buf][k][row] transposed
    __shared__ __align__(16) float ws[2][32][68];  // [buf][k][col]

    const int tid = threadIdx.x;
    const int tx  = tid & 15;   // col group *4
    const int ty  = tid >> 4;   // row group *4

    const int xr  = tid >> 2;          // 0..63 row
    const int xk4 = (tid & 3) * 4;     // k 0..12 (+16)
    const int wk  = tid >> 4;          // 0..15 k (+16)
    const int wc4 = (tid & 15) * 4;    // col

    ull acc[4][2];
    #pragma unroll
    for (int i = 0; i < 4; i++) { acc[i][0] = 0ull; acc[i][1] = 0ull; }

    const float* xrow = &x[((size_t)b * NT + t0 + xr) * ND];

    // preload chunk 0 into buf 0
    #pragma unroll
    for (int half = 0; half < 2; half++) {
        const int k4 = xk4 + 16 * half;
        float4 v = *(const float4*)&xrow[k4];
        xs[0][k4 + 0][xr] = v.x;
        xs[0][k4 + 1][xr] = v.y;
        xs[0][k4 + 2][xr] = v.z;
        xs[0][k4 + 3][xr] = v.w;
        const int k = wk + 16 * half;
        *(float4*)&ws[0][k][wc4] = *(const float4*)&W[(size_t)k * NH + wc4];
    }
    __syncthreads();

    int buf = 0;
    for (int kb = 0; kb < ND; kb += 32) {
        if (kb + 32 < ND) {
            const int nb = buf ^ 1;
            #pragma unroll
            for (int half = 0; half < 2; half++) {
                const int k4 = xk4 + 16 * half;
                float4 v = *(const float4*)&xrow[kb + 32 + k4];
                xs[nb][k4 + 0][xr] = v.x;
                xs[nb][k4 + 1][xr] = v.y;
                xs[nb][k4 + 2][xr] = v.z;
                xs[nb][k4 + 3][xr] = v.w;
                const int k = wk + 16 * half;
                *(float4*)&ws[nb][k][wc4] =
                    *(const float4*)&W[(size_t)(kb + 32 + k) * NH + wc4];
            }
        }
        #pragma unroll
        for (int kk = 0; kk < 32; kk++) {
            float4 a = *(const float4*)&xs[buf][kk][ty * 4];
            ulonglong2 wv = *(const ulonglong2*)&ws[buf][kk][tx * 4];
            ull a0 = pack2s(a.x), a1 = pack2s(a.y), a2 = pack2s(a.z), a3 = pack2s(a.w);
            fma2(acc[0][0], a0, wv.x); fma2(acc[0][1], a0, wv.y);
            fma2(acc[1][0], a1, wv.x); fma2(acc[1][1], a1, wv.y);
            fma2(acc[2][0], a2, wv.x); fma2(acc[2][1], a2, wv.y);
            fma2(acc[3][0], a3, wv.x); fma2(acc[3][1], a3, wv.y);
        }
        __syncthreads();
        buf ^= 1;
    }

    if (z < 2) {  // transposed store OT[b][col][t]
        float* __restrict__ OT = (z == 0) ? g_qT : g_kT;
        float2 u[4][2];
        #pragma unroll
        for (int i = 0; i < 4; i++) {
            u[i][0] = unpack2(acc[i][0]);
            u[i][1] = unpack2(acc[i][1]);
        }
        const size_t b0 = (size_t)(b * NH + tx * 4) * NT + t0 + ty * 4;
        *(float4*)&OT[b0]          = make_float4(u[0][0].x, u[1][0].x, u[2][0].x, u[3][0].x);
        *(float4*)&OT[b0 + NT]     = make_float4(u[0][0].y, u[1][0].y, u[2][0].y, u[3][0].y);
        *(float4*)&OT[b0 + 2 * NT] = make_float4(u[0][1].x, u[1][1].x, u[2][1].x, u[3][1].x);
        *(float4*)&OT[b0 + 3 * NT] = make_float4(u[0][1].y, u[1][1].y, u[2][1].y, u[3][1].y);
    } else {      // V row-major
        #pragma unroll
        for (int i = 0; i < 4; i++) {
            ulonglong2 st; st.x = acc[i][0]; st.y = acc[i][1];
            *(ulonglong2*)&g_v[((size_t)b * NT + t0 + ty * 4 + i) * NH + tx * 4] = st;
        }
    }
}

// ---------------------------------------------------------------------------
// Flash-attention partials: BQ=64, BK=128, 128 threads, split-K via z.
// (identical to the measured-good round-4 version)
// ---------------------------------------------------------------------------
#define OFF_QT 0                    // QsT [64h][68]
#define OFF_KT 4352                 // KsT [64h][132]
#define OFF_VS 12800                // Vs  [128k][68]
#define OFF_PS 21504                // Ps  [64r][132]
#define OFF_CR 29952                // corr[64]
#define OFF_OS OFF_KT               // Os  [64r][68] overlays KsT (dead after loop)
#define SM_FLOATS 30016
#define SM_BYTES (SM_FLOATS * 4)

__global__ void attn_part(const int* __restrict__ valid_lens)
{
    extern __shared__ float sm[];
    const int b  = blockIdx.y;
    const int q0 = blockIdx.x * 64;
    const int s  = blockIdx.z;
    int L = valid_lens[b];
    if (L < 0) L = 0;
    if (L > NT) L = NT;
    if (q0 >= L) return;

    const int tid = threadIdx.x;
    const int kg  = tid & 15;          // S: 16 key groups *8
    const int rg  = tid >> 4;          // S: 8 row groups *8
    const int hg  = tid & 7;           // PV: 8 h groups *8
    const int rg2 = (tid >> 3) & 7;    // PV: 8 row groups *8
    const int ks  = tid >> 6;          // PV: key half

    const int kend = (q0 + 64 < L) ? (q0 + 64) : L;
    const int C = (((kend + SPL - 1) / SPL) + 127) & ~127;
    const int jb = s * C;
    const int je = (jb + C < kend) ? (jb + C) : kend;

    if (jb >= je) {  // empty split: write neutral partials
        const float4 z4 = make_float4(0.f, 0.f, 0.f, 0.f);
        #pragma unroll
        for (int i = 0; i < 8; i++) {
            int idx = tid + 128 * i;
            int row = idx >> 4, h4 = (idx & 15) * 4;
            *(float4*)&g_po[((size_t)(b * NT + q0 + row) * SPL + s) * NH + h4] = z4;
        }
        if (tid < 64) {
            g_pm[(size_t)(b * NT + q0 + tid) * SPL + s] = -1e30f;
            g_pl[(size_t)(b * NT + q0 + tid) * SPL + s] = 0.f;
        }
        return;
    }

    // load QsT
    #pragma unroll
    for (int i = 0; i < 8; i++) {
        int idx = tid + 128 * i;
        int h = idx >> 4, r4 = (idx & 15) * 4;
        *(float4*)&sm[OFF_QT + h * 68 + r4] =
            *(const float4*)&g_qT[(size_t)(b * NH + h) * NT + q0 + r4];
    }

    float m[8], l[8];
    #pragma unroll
    for (int i = 0; i < 8; i++) { m[i] = -1e30f; l[i] = 0.f; }
    ull o[8][4];
    #pragma unroll
    for (int i = 0; i < 8; i++)
        #pragma unroll
        for (int p = 0; p < 4; p++) o[i][p] = 0ull;

    for (int j0 = jb; j0 < je; j0 += 128) {
        __syncthreads();
        #pragma unroll
        for (int i = 0; i < 16; i++) {
            int idx = tid + 128 * i;
            int h = idx >> 5, k4 = (idx & 31) * 4;
            *(float4*)&sm[OFF_KT + h * 132 + k4] =
                *(const float4*)&g_kT[(size_t)(b * NH + h) * NT + j0 + k4];
            int key = idx >> 4, h4 = (idx & 15) * 4;
            *(float4*)&sm[OFF_VS + key * 68 + h4] =
                *(const float4*)&g_v[((size_t)b * NT + j0 + key) * NH + h4];
        }
        __syncthreads();

        // S = Q K^T  (8 rows x 8 keys per thread, key-paired)
        ull sacc[8][4];
        #pragma unroll
        for (int i = 0; i < 8; i++)
            #pragma unroll
            for (int p = 0; p < 4; p++) sacc[i][p] = 0ull;

        for (int h = 0; h < NH; h++) {
            float4 qa = *(const float4*)&sm[OFF_QT + h * 68 + rg * 8];
            float4 qb = *(const float4*)&sm[OFF_QT + h * 68 + rg * 8 + 4];
            ulonglong2 ka = *(const ulonglong2*)&sm[OFF_KT + h * 132 + kg * 8];
            ulonglong2 kb2 = *(const ulonglong2*)&sm[OFF_KT + h * 132 + kg * 8 + 4];
            ull qq[8] = { pack2s(qa.x), pack2s(qa.y), pack2s(qa.z), pack2s(qa.w),
                          pack2s(qb.x), pack2s(qb.y), pack2s(qb.z), pack2s(qb.w) };
            ull kk[4] = { ka.x, ka.y, kb2.x, kb2.y };
            #pragma unroll
            for (int i = 0; i < 8; i++)
                #pragma unroll
                for (int p = 0; p < 4; p++)
                    fma2(sacc[i][p], qq[i], kk[p]);
        }

        // softmax per row; write P + corr
        #pragma unroll
        for (int i = 0; i < 8; i++) {
            const int q = q0 + rg * 8 + i;
            float sv[8];
            #pragma unroll
            for (int p = 0; p < 4; p++) {
                float2 u = unpack2(sacc[i][p]);
                sv[2 * p] = u.x; sv[2 * p + 1] = u.y;
            }
            #pragma unroll
            for (int c = 0; c < 8; c++) {
                int key = j0 + kg * 8 + c;
                bool valid = (key <= q) && (key < L);
                sv[c] = valid ? sv[c] * 0.125f : -1e30f;
            }
            float tm = sv[0];
            #pragma unroll
            for (int c = 1; c < 8; c++) tm = fmaxf(tm, sv[c]);
            #pragma unroll
            for (int off = 1; off < 16; off <<= 1)
                tm = fmaxf(tm, __shfl_xor_sync(0xffffffffu, tm, off));
            const float mn = fmaxf(m[i], tm);
            const float corr = __expf(m[i] - mn);
            float pj[8], psum = 0.f;
            #pragma unroll
            for (int c = 0; c < 8; c++) {
                pj[c] = (sv[c] > -1e29f) ? __expf(sv[c] - mn) : 0.f;
                psum += pj[c];
            }
            #pragma unroll
            for (int off = 1; off < 16; off <<= 1)
                psum += __shfl_xor_sync(0xffffffffu, psum, off);
            l[i] = l[i] * corr + psum;
            m[i] = mn;
            *(float4*)&sm[OFF_PS + (rg * 8 + i) * 132 + kg * 8] =
                make_float4(pj[0], pj[1], pj[2], pj[3]);
            *(float4*)&sm[OFF_PS + (rg * 8 + i) * 132 + kg * 8 + 4] =
                make_float4(pj[4], pj[5], pj[6], pj[7]);
            if (kg == 0) sm[OFF_CR + rg * 8 + i] = corr;
        }
        __syncthreads();

        // rescale O, then O += P V over this thread's key half
        #pragma unroll
        for (int i = 0; i < 8; i++) {
            ull c2 = pack2s(sm[OFF_CR + rg2 * 8 + i]);
            #pragma unroll
            for (int p = 0; p < 4; p++) mul2(o[i][p], c2);
        }
        for (int k = 0; k < 64; k++) {
            const int key = ks * 64 + k;
            ulonglong2 va = *(const ulonglong2*)&sm[OFF_VS + key * 68 + hg * 8];
            ulonglong2 vb = *(const ulonglong2*)&sm[OFF_VS + key * 68 + hg * 8 + 4];
            ull vv[4] = { va.x, va.y, vb.x, vb.y };
            #pragma unroll
            for (int i = 0; i < 8; i++) {
                ull pp = pack2s(sm[OFF_PS + (rg2 * 8 + i) * 132 + key]);
                #pragma unroll
                for (int p = 0; p < 4; p++)
                    fma2(o[i][p], pp, vv[p]);
            }
        }
    }

    // write pm/pl (S mapping)
    if (kg == 0) {
        #pragma unroll
        for (int i = 0; i < 8; i++) {
            const size_t pi = (size_t)(b * NT + q0 + rg * 8 + i) * SPL + s;
            g_pm[pi] = m[i];
            g_pl[pi] = l[i];
        }
    }

    // merge ks halves, write po
    __syncthreads();
    if (ks == 1) {
        #pragma unroll
        for (int i = 0; i < 8; i++) {
            float2 u0 = unpack2(o[i][0]), u1 = unpack2(o[i][1]);
            float2 u2 = unpack2(o[i][2]), u3 = unpack2(o[i][3]);
            *(float4*)&sm[OFF_OS + (rg2 * 8 + i) * 68 + hg * 8] =
                make_float4(u0.x, u0.y, u1.x, u1.y);
            *(float4*)&sm[OFF_OS + (rg2 * 8 + i) * 68 + hg * 8 + 4] =
                make_float4(u2.x, u2.y, u3.x, u3.y);
        }
    }
    __syncthreads();
    if (ks == 0) {
        #pragma unroll
        for (int i = 0; i < 8; i++) {
            float2 u0 = unpack2(o[i][0]), u1 = unpack2(o[i][1]);
            float2 u2 = unpack2(o[i][2]), u3 = unpack2(o[i][3]);
            float4 s0 = *(const float4*)&sm[OFF_OS + (rg2 * 8 + i) * 68 + hg * 8];
            float4 s1 = *(const float4*)&sm[OFF_OS + (rg2 * 8 + i) * 68 + hg * 8 + 4];
            const size_t po = ((size_t)(b * NT + q0 + rg2 * 8 + i) * SPL + s) * NH + hg * 8;
            *(float4*)&g_po[po] =
                make_float4(u0.x + s0.x, u0.y + s0.y, u1.x + s0.z, u1.y + s0.w);
            *(float4*)&g_po[po + 4] =
                make_float4(u2.x + s1.x, u2.y + s1.y, u3.x + s1.z, u3.y + s1.w);
        }
    }
}

// ---------------------------------------------------------------------------
// Combine split-K partials.
// ---------------------------------------------------------------------------
__global__ __launch_bounds__(128) void attn_combine(
    const int* __restrict__ valid_lens, float* __restrict__ out)
{
    const int b   = blockIdx.y;
    const int tid = threadIdx.x;
    const int row = tid >> 3;
    const int t8  = tid & 7;
    const int q   = blockIdx.x * 16 + row;
    int L = valid_lens[b];
    if (L < 0) L = 0;
    if (L > NT) L = NT;

    const size_t base0 = (size_t)(b * NT + q) * SPL;
    float ms[SPL], mstar = -1e30f;
    #pragma unroll
    for (int s = 0; s < SPL; s++) {
        ms[s] = g_pm[base0 + s];
        mstar = fmaxf(mstar, ms[s]);
    }
    float l = 0.f;
    float4 oA = make_float4(0.f, 0.f, 0.f, 0.f);
    float4 oB = make_float4(0.f, 0.f, 0.f, 0.f);
    #pragma unroll
    for (int s = 0; s < SPL; s++) {
        const float w = (ms[s] > -1e29f) ? __expf(ms[s] - mstar) : 0.f;
        l += g_pl[base0 + s] * w;
        float4 a = *(const float4*)&g_po[(base0 + s) * NH + t8 * 4];
        float4 c = *(const float4*)&g_po[(base0 + s) * NH + 32 + t8 * 4];
        oA.x += a.x * w; oA.y += a.y * w; oA.z += a.z * w; oA.w += a.w * w;
        oB.x += c.x * w; oB.y += c.y * w; oB.z += c.z * w; oB.w += c.w * w;
    }
    const float inv = (q < L && l > 0.f) ? (1.f / l) : 0.f;
    const size_t ob = ((size_t)b * NT + q) * NH;
    *(float4*)&out[ob + t8 * 4] =
        make_float4(oA.x * inv, oA.y * inv, oA.z * inv, oA.w * inv);
    *(float4*)&out[ob + 32 + t8 * 4] =
        make_float4(oB.x * inv, oB.y * inv, oB.z * inv, oB.w * inv);
}

extern "C" void kernel_launch(void* const* d_in, const int* in_sizes, int n_in,
                              void* d_out, int out_size)
{
    const float* x  = (const float*)d_in[0];
    const float* Wq = (const float*)d_in[1];
    const float* Wk = (const float*)d_in[2];
    const float* Wv = (const float*)d_in[3];
    const int*   vl = (const int*)d_in[4];
    float* out = (float*)d_out;

    cudaFuncSetAttribute(attn_part, cudaFuncAttributeMaxDynamicSharedMemorySize, SM_BYTES);

    proj_kernel<<<dim3(NT / 64, NB, 3), 256>>>(x, Wq, Wk, Wv, vl);
    attn_part<<<dim3(NT / 64, NB, SPL), 128, SM_BYTES>>>(vl);
    attn_combine<<<dim3(NT / 16, NB), 128>>>(vl, out);
}

// round 8
// speedup vs baseline: 1.2911x; 1.0418x over previous
#include <cuda_runtime.h>

#define NB 8
#define NT 2048
#define ND 1024
#define NH 64
#define SPL 2

typedef unsigned long long ull;

__device__ __forceinline__ ull pack2s(float v) {
    ull r; asm("mov.b64 %0, {%1, %2};" : "=l"(r) : "f"(v), "f"(v)); return r;
}
__device__ __forceinline__ void fma2(ull& d, ull a, ull b) {
    asm("fma.rn.f32x2 %0, %1, %2, %0;" : "+l"(d) : "l"(a), "l"(b));
}
__device__ __forceinline__ void mul2(ull& d, ull a) {
    asm("mul.rn.f32x2 %0, %0, %1;" : "+l"(d) : "l"(a));
}
__device__ __forceinline__ float2 unpack2(ull v) {
    float2 r; asm("mov.b64 {%0, %1}, %2;" : "=f"(r.x), "=f"(r.y) : "l"(v)); return r;
}

// Q,K transposed [b][h][t]; V row-major [b][t][h]; split-K partials.
__device__ float g_qT[NB * NH * NT];
__device__ float g_kT[NB * NH * NT];
__device__ float g_v [NB * NT * NH];
__device__ float g_po[(size_t)NB * NT * SPL * NH];
__device__ float g_pm[NB * NT * SPL];
__device__ float g_pl[NB * NT * SPL];

// ---------------------------------------------------------------------------
// Projection: 64x64 tile of matrix z per block. 256 threads, 4x4/thread,
// BK=32, double-buffered smem with REGISTER-STAGED prefetch:
//   LDG next chunk -> regs ; compute current ; STS regs ; sync.
// ---------------------------------------------------------------------------
__global__ __launch_bounds__(256) void proj_kernel(
    const float* __restrict__ x, const float* __restrict__ Wq,
    const float* __restrict__ Wk, const float* __restrict__ Wv,
    const int* __restrict__ valid_lens)
{
    const int b  = blockIdx.y;
    const int t0 = blockIdx.x * 64;
    const int z  = blockIdx.z;
    int L = valid_lens[b];
    if (L < 0) L = 0;
    if (L > NT) L = NT;
    if (t0 >= L) return;

    const float* __restrict__ W = (z == 0) ? Wq : ((z == 1) ? Wk : Wv);

    __shared__ __align__(16) float xs[2][32][68];  // [buf][k][row] transposed
    __shared__ __align__(16) float ws[2][32][68];  // [buf][k][col]

    const int tid = threadIdx.x;
    const int tx  = tid & 15;   // col group *4
    const int ty  = tid >> 4;   // row group *4

    const int xr  = tid >> 2;          // 0..63 row
    const int xk4 = (tid & 3) * 4;     // k 0..12 (+16)
    const int wk  = tid >> 4;          // 0..15 k (+16)
    const int wc4 = (tid & 15) * 4;    // col

    ull acc[4][2];
    #pragma unroll
    for (int i = 0; i < 4; i++) { acc[i][0] = 0ull; acc[i][1] = 0ull; }

    const float* xrow = &x[((size_t)b * NT + t0 + xr) * ND];

    // preload chunk 0 into buf 0
    #pragma unroll
    for (int half = 0; half < 2; half++) {
        const int k4 = xk4 + 16 * half;
        float4 v = *(const float4*)&xrow[k4];
        xs[0][k4 + 0][xr] = v.x;
        xs[0][k4 + 1][xr] = v.y;
        xs[0][k4 + 2][xr] = v.z;
        xs[0][k4 + 3][xr] = v.w;
        const int k = wk + 16 * half;
        *(float4*)&ws[0][k][wc4] = *(const float4*)&W[(size_t)k * NH + wc4];
    }
    __syncthreads();

    int buf = 0;
    for (int kb = 0; kb < ND; kb += 32) {
        const bool has_next = (kb + 32 < ND);
        float4 pxv[2], pwv[2];
        if (has_next) {   // LDG next chunk into registers NOW (latency overlapped)
            #pragma unroll
            for (int half = 0; half < 2; half++) {
                pxv[half] = *(const float4*)&xrow[kb + 32 + xk4 + 16 * half];
                pwv[half] = *(const float4*)&W[(size_t)(kb + 32 + wk + 16 * half) * NH + wc4];
            }
        }
        #pragma unroll
        for (int kk = 0; kk < 32; kk++) {
            float4 a = *(const float4*)&xs[buf][kk][ty * 4];
            ulonglong2 wv = *(const ulonglong2*)&ws[buf][kk][tx * 4];
            ull a0 = pack2s(a.x), a1 = pack2s(a.y), a2 = pack2s(a.z), a3 = pack2s(a.w);
            fma2(acc[0][0], a0, wv.x); fma2(acc[0][1], a0, wv.y);
            fma2(acc[1][0], a1, wv.x); fma2(acc[1][1], a1, wv.y);
            fma2(acc[2][0], a2, wv.x); fma2(acc[2][1], a2, wv.y);
            fma2(acc[3][0], a3, wv.x); fma2(acc[3][1], a3, wv.y);
        }
        if (has_next) {   // STS staged regs into the other buffer
            const int nb = buf ^ 1;
            #pragma unroll
            for (int half = 0; half < 2; half++) {
                const int k4 = xk4 + 16 * half;
                xs[nb][k4 + 0][xr] = pxv[half].x;
                xs[nb][k4 + 1][xr] = pxv[half].y;
                xs[nb][k4 + 2][xr] = pxv[half].z;
                xs[nb][k4 + 3][xr] = pxv[half].w;
                *(float4*)&ws[nb][wk + 16 * half][wc4] = pwv[half];
            }
        }
        __syncthreads();
        buf ^= 1;
    }

    if (z < 2) {  // transposed store OT[b][col][t]
        float* __restrict__ OT = (z == 0) ? g_qT : g_kT;
        float2 u[4][2];
        #pragma unroll
        for (int i = 0; i < 4; i++) {
            u[i][0] = unpack2(acc[i][0]);
            u[i][1] = unpack2(acc[i][1]);
        }
        const size_t b0 = (size_t)(b * NH + tx * 4) * NT + t0 + ty * 4;
        *(float4*)&OT[b0]          = make_float4(u[0][0].x, u[1][0].x, u[2][0].x, u[3][0].x);
        *(float4*)&OT[b0 + NT]     = make_float4(u[0][0].y, u[1][0].y, u[2][0].y, u[3][0].y);
        *(float4*)&OT[b0 + 2 * NT] = make_float4(u[0][1].x, u[1][1].x, u[2][1].x, u[3][1].x);
        *(float4*)&OT[b0 + 3 * NT] = make_float4(u[0][1].y, u[1][1].y, u[2][1].y, u[3][1].y);
    } else {      // V row-major
        #pragma unroll
        for (int i = 0; i < 4; i++) {
            ulonglong2 st; st.x = acc[i][0]; st.y = acc[i][1];
            *(ulonglong2*)&g_v[((size_t)b * NT + t0 + ty * 4 + i) * NH + tx * 4] = st;
        }
    }
}

// ---------------------------------------------------------------------------
// Flash-attention partials: BQ=64, BK=64, 128 threads, split-K via z.
// smem ~70KB -> 3 blocks/SM (12 warps) for latency hiding.
// ---------------------------------------------------------------------------
#define PSTRIDE 70
#define OFF_QT 0                       // QsT [64h][68]
#define OFF_KT (64 * 68)               // KsT [64h][68]
#define OFF_VS (OFF_KT + 64 * 68)      // Vs  [64k][68]
#define OFF_PS (OFF_VS + 64 * 68)      // Ps  [64r][70]
#define OFF_CR (OFF_PS + 64 * PSTRIDE) // corr[64]
#define OFF_OS OFF_KT                  // Os  [64r][68] overlays KsT (dead after loop)
#define SM_FLOATS (OFF_CR + 64)
#define SM_BYTES (SM_FLOATS * 4)

__global__ void attn_part(const int* __restrict__ valid_lens)
{
    extern __shared__ float sm[];
    const int b  = blockIdx.y;
    const int q0 = blockIdx.x * 64;
    const int s  = blockIdx.z;
    int L = valid_lens[b];
    if (L < 0) L = 0;
    if (L > NT) L = NT;
    if (q0 >= L) return;

    const int tid = threadIdx.x;
    const int kg  = tid & 15;          // S: 16 key groups *4
    const int rg  = tid >> 4;          // S: 8 row groups *8
    const int hg  = tid & 7;           // PV: 8 h groups *8
    const int rg2 = (tid >> 3) & 7;    // PV: 8 row groups *8
    const int ks  = tid >> 6;          // PV: key half (32 keys each)

    const int kend = (q0 + 64 < L) ? (q0 + 64) : L;
    const int C  = (((kend + SPL - 1) / SPL) + 63) & ~63;
    const int jb = s * C;
    const int je = (jb + C < kend) ? (jb + C) : kend;

    if (jb >= je) {  // empty split: neutral partials
        const float4 z4 = make_float4(0.f, 0.f, 0.f, 0.f);
        #pragma unroll
        for (int i = 0; i < 8; i++) {
            int idx = tid + 128 * i;
            int row = idx >> 4, h4 = (idx & 15) * 4;
            *(float4*)&g_po[((size_t)(b * NT + q0 + row) * SPL + s) * NH + h4] = z4;
        }
        if (tid < 64) {
            g_pm[(size_t)(b * NT + q0 + tid) * SPL + s] = -1e30f;
            g_pl[(size_t)(b * NT + q0 + tid) * SPL + s] = 0.f;
        }
        return;
    }

    // load QsT
    #pragma unroll
    for (int i = 0; i < 8; i++) {
        int idx = tid + 128 * i;
        int h = idx >> 4, r4 = (idx & 15) * 4;
        *(float4*)&sm[OFF_QT + h * 68 + r4] =
            *(const float4*)&g_qT[(size_t)(b * NH + h) * NT + q0 + r4];
    }

    float m[8], l[8];
    #pragma unroll
    for (int i = 0; i < 8; i++) { m[i] = -1e30f; l[i] = 0.f; }
    ull o[8][4];
    #pragma unroll
    for (int i = 0; i < 8; i++)
        #pragma unroll
        for (int p = 0; p < 4; p++) o[i][p] = 0ull;

    for (int j0 = jb; j0 < je; j0 += 64) {
        __syncthreads();
        #pragma unroll
        for (int i = 0; i < 8; i++) {
            int idx = tid + 128 * i;
            int h = idx >> 4, k4 = (idx & 15) * 4;
            *(float4*)&sm[OFF_KT + h * 68 + k4] =
                *(const float4*)&g_kT[(size_t)(b * NH + h) * NT + j0 + k4];
            int key = idx >> 4, h4 = (idx & 15) * 4;
            *(float4*)&sm[OFF_VS + key * 68 + h4] =
                *(const float4*)&g_v[((size_t)b * NT + j0 + key) * NH + h4];
        }
        __syncthreads();

        // ---- S = Q K^T : 8 rows x 4 keys per thread (keys kg*4..+3)
        ull sacc[8][2];
        #pragma unroll
        for (int i = 0; i < 8; i++) { sacc[i][0] = 0ull; sacc[i][1] = 0ull; }

        #pragma unroll 8
        for (int h = 0; h < NH; h++) {
            float4 qa = *(const float4*)&sm[OFF_QT + h * 68 + rg * 8];
            float4 qb = *(const float4*)&sm[OFF_QT + h * 68 + rg * 8 + 4];
            ulonglong2 kk2 = *(const ulonglong2*)&sm[OFF_KT + h * 68 + kg * 4];
            ull qq[8] = { pack2s(qa.x), pack2s(qa.y), pack2s(qa.z), pack2s(qa.w),
                          pack2s(qb.x), pack2s(qb.y), pack2s(qb.z), pack2s(qb.w) };
            #pragma unroll
            for (int i = 0; i < 8; i++) {
                fma2(sacc[i][0], qq[i], kk2.x);
                fma2(sacc[i][1], qq[i], kk2.y);
            }
        }

        // ---- softmax per row
        #pragma unroll
        for (int i = 0; i < 8; i++) {
            const int q = q0 + rg * 8 + i;
            float2 u0 = unpack2(sacc[i][0]), u1 = unpack2(sacc[i][1]);
            float sv[4] = { u0.x, u0.y, u1.x, u1.y };
            #pragma unroll
            for (int c = 0; c < 4; c++) {
                int key = j0 + kg * 4 + c;
                bool valid = (key <= q) && (key < L);
                sv[c] = valid ? sv[c] * 0.125f : -1e30f;
            }
            float tm = fmaxf(fmaxf(sv[0], sv[1]), fmaxf(sv[2], sv[3]));
            #pragma unroll
            for (int off = 1; off < 16; off <<= 1)
                tm = fmaxf(tm, __shfl_xor_sync(0xffffffffu, tm, off));
            const float mn = fmaxf(m[i], tm);
            const float corr = __expf(m[i] - mn);
            float pj[4], psum = 0.f;
            #pragma unroll
            for (int c = 0; c < 4; c++) {
                pj[c] = (sv[c] > -1e29f) ? __expf(sv[c] - mn) : 0.f;
                psum += pj[c];
            }
            #pragma unroll
            for (int off = 1; off < 16; off <<= 1)
                psum += __shfl_xor_sync(0xffffffffu, psum, off);
            l[i] = l[i] * corr + psum;
            m[i] = mn;
            const int rb = OFF_PS + (rg * 8 + i) * PSTRIDE + kg * 4;
            *(float2*)&sm[rb]     = make_float2(pj[0], pj[1]);
            *(float2*)&sm[rb + 2] = make_float2(pj[2], pj[3]);
            if (kg == 0) sm[OFF_CR + rg * 8 + i] = corr;
        }
        __syncthreads();

        // ---- rescale O, then O += P V over this thread's 32-key half
        #pragma unroll
        for (int i = 0; i < 8; i++) {
            ull c2 = pack2s(sm[OFF_CR + rg2 * 8 + i]);
            #pragma unroll
            for (int p = 0; p < 4; p++) mul2(o[i][p], c2);
        }
        for (int k = 0; k < 32; k++) {
            const int key = ks * 32 + k;
            ulonglong2 va = *(const ulonglong2*)&sm[OFF_VS + key * 68 + hg * 8];
            ulonglong2 vb = *(const ulonglong2*)&sm[OFF_VS + key * 68 + hg * 8 + 4];
            ull vv[4] = { va.x, va.y, vb.x, vb.y };
            #pragma unroll
            for (int i = 0; i < 8; i++) {
                ull pp = pack2s(sm[OFF_PS + (rg2 * 8 + i) * PSTRIDE + key]);
                #pragma unroll
                for (int p = 0; p < 4; p++)
                    fma2(o[i][p], pp, vv[p]);
            }
        }
    }

    // write pm/pl (S mapping)
    if (kg == 0) {
        #pragma unroll
        for (int i = 0; i < 8; i++) {
            const size_t pi = (size_t)(b * NT + q0 + rg * 8 + i) * SPL + s;
            g_pm[pi] = m[i];
            g_pl[pi] = l[i];
        }
    }

    // merge ks halves, write po
    __syncthreads();
    if (ks == 1) {
        #pragma unroll
        for (int i = 0; i < 8; i++) {
            float2 u0 = unpack2(o[i][0]), u1 = unpack2(o[i][1]);
            float2 u2 = unpack2(o[i][2]), u3 = unpack2(o[i][3]);
            *(float4*)&sm[OFF_OS + (rg2 * 8 + i) * 68 + hg * 8] =
                make_float4(u0.x, u0.y, u1.x, u1.y);
            *(float4*)&sm[OFF_OS + (rg2 * 8 + i) * 68 + hg * 8 + 4] =
                make_float4(u2.x, u2.y, u3.x, u3.y);
        }
    }
    __syncthreads();
    if (ks == 0) {
        #pragma unroll
        for (int i = 0; i < 8; i++) {
            float2 u0 = unpack2(o[i][0]), u1 = unpack2(o[i][1]);
            float2 u2 = unpack2(o[i][2]), u3 = unpack2(o[i][3]);
            float4 s0 = *(const float4*)&sm[OFF_OS + (rg2 * 8 + i) * 68 + hg * 8];
            float4 s1 = *(const float4*)&sm[OFF_OS + (rg2 * 8 + i) * 68 + hg * 8 + 4];
            const size_t po = ((size_t)(b * NT + q0 + rg2 * 8 + i) * SPL + s) * NH + hg * 8;
            *(float4*)&g_po[po] =
                make_float4(u0.x + s0.x, u0.y + s0.y, u1.x + s0.z, u1.y + s0.w);
            *(float4*)&g_po[po + 4] =
                make_float4(u2.x + s1.x, u2.y + s1.y, u3.x + s1.z, u3.y + s1.w);
        }
    }
}

// ---------------------------------------------------------------------------
// Combine split-K partials.
// ---------------------------------------------------------------------------
__global__ __launch_bounds__(128) void attn_combine(
    const int* __restrict__ valid_lens, float* __restrict__ out)
{
    const int b   = blockIdx.y;
    const int tid = threadIdx.x;
    const int row = tid >> 3;
    const int t8  = tid & 7;
    const int q   = blockIdx.x * 16 + row;
    int L = valid_lens[b];
    if (L < 0) L = 0;
    if (L > NT) L = NT;

    const size_t base0 = (size_t)(b * NT + q) * SPL;
    float ms[SPL], mstar = -1e30f;
    #pragma unroll
    for (int s = 0; s < SPL; s++) {
        ms[s] = g_pm[base0 + s];
        mstar = fmaxf(mstar, ms[s]);
    }
    float l = 0.f;
    float4 oA = make_float4(0.f, 0.f, 0.f, 0.f);
    float4 oB = make_float4(0.f, 0.f, 0.f, 0.f);
    #pragma unroll
    for (int s = 0; s < SPL; s++) {
        const float w = (ms[s] > -1e29f) ? __expf(ms[s] - mstar) : 0.f;
        l += g_pl[base0 + s] * w;
        float4 a = *(const float4*)&g_po[(base0 + s) * NH + t8 * 4];
        float4 c = *(const float4*)&g_po[(base0 + s) * NH + 32 + t8 * 4];
        oA.x += a.x * w; oA.y += a.y * w; oA.z += a.z * w; oA.w += a.w * w;
        oB.x += c.x * w; oB.y += c.y * w; oB.z += c.z * w; oB.w += c.w * w;
    }
    const float inv = (q < L && l > 0.f) ? (1.f / l) : 0.f;
    const size_t ob = ((size_t)b * NT + q) * NH;
    *(float4*)&out[ob + t8 * 4] =
        make_float4(oA.x * inv, oA.y * inv, oA.z * inv, oA.w * inv);
    *(float4*)&out[ob + 32 + t8 * 4] =
        make_float4(oB.x * inv, oB.y * inv, oB.z * inv, oB.w * inv);
}

extern "C" void kernel_launch(void* const* d_in, const int* in_sizes, int n_in,
                              void* d_out, int out_size)
{
    const float* x  = (const float*)d_in[0];
    const float* Wq = (const float*)d_in[1];
    const float* Wk = (const float*)d_in[2];
    const float* Wv = (const float*)d_in[3];
    const int*   vl = (const int*)d_in[4];
    float* out = (float*)d_out;

    cudaFuncSetAttribute(attn_part, cudaFuncAttributeMaxDynamicSharedMemorySize, SM_BYTES);

    proj_kernel<<<dim3(NT / 64, NB, 3), 256>>>(x, Wq, Wk, Wv, vl);
    attn_part<<<dim3(NT / 64, NB, SPL), 128, SM_BYTES>>>(vl);
    attn_combine<<<dim3(NT / 16, NB), 128>>>(vl, out);
}

// round 9
// speedup vs baseline: 1.3090x; 1.0139x over previous
#include <cuda_runtime.h>

#define NB 8
#define NT 2048
#define ND 1024
#define NH 64
#define SPL 2

typedef unsigned long long ull;

__device__ __forceinline__ ull pack2s(float v) {
    ull r; asm("mov.b64 %0, {%1, %2};" : "=l"(r) : "f"(v), "f"(v)); return r;
}
__device__ __forceinline__ void fma2(ull& d, ull a, ull b) {
    asm("fma.rn.f32x2 %0, %1, %2, %0;" : "+l"(d) : "l"(a), "l"(b));
}
__device__ __forceinline__ void mul2(ull& d, ull a) {
    asm("mul.rn.f32x2 %0, %0, %1;" : "+l"(d) : "l"(a));
}
__device__ __forceinline__ float2 unpack2(ull v) {
    float2 r; asm("mov.b64 {%0, %1}, %2;" : "=f"(r.x), "=f"(r.y) : "l"(v)); return r;
}

// Q,K transposed [b][h][t]; V row-major [b][t][h]; split-K partials.
__device__ float g_qT[NB * NH * NT];
__device__ float g_kT[NB * NH * NT];
__device__ float g_v [NB * NT * NH];
__device__ float g_po[(size_t)NB * NT * SPL * NH];
__device__ float g_pm[NB * NT * SPL];
__device__ float g_pl[NB * NT * SPL];

// ---------------------------------------------------------------------------
// Fused projection: one block computes a 32-row x 192-col (q|k|v) tile.
// 128 threads, 4 rows x 12 cols (6 f32x2 pairs) per thread, BK=16,
// register-staged double buffer. x is loaded ONCE for all three matrices.
// ---------------------------------------------------------------------------
__global__ __launch_bounds__(128) void proj_kernel(
    const float* __restrict__ x, const float* __restrict__ Wq,
    const float* __restrict__ Wk, const float* __restrict__ Wv,
    const int* __restrict__ valid_lens)
{
    const int b  = blockIdx.y;
    const int t0 = blockIdx.x * 32;
    int L = valid_lens[b];
    if (L < 0) L = 0;
    if (L > NT) L = NT;
    if (t0 >= L) return;

    __shared__ __align__(16) float xs[2][16][40];   // [buf][k][row] transposed
    __shared__ __align__(16) float ws[2][16][196];  // [buf][k][col 0..191 = q|k|v]

    const int tid = threadIdx.x;
    const int tx  = tid & 15;   // col group *12
    const int ty  = tid >> 4;   // row group *4 (0..7)

    // loaders
    const int xr  = tid & 31;          // row 0..31
    const int xk4 = (tid >> 5) * 4;    // k base 0,4,8,12
    const int wk  = tid >> 4;          // k 0..7 (+8)
    const int wc4 = (tid & 15) * 4;    // col-in-matrix 0..60

    ull acc[4][6];
    #pragma unroll
    for (int i = 0; i < 4; i++)
        #pragma unroll
        for (int j = 0; j < 6; j++) acc[i][j] = 0ull;

    const float* xrow = &x[((size_t)b * NT + t0 + xr) * ND];
    const float* Wm[3] = { Wq, Wk, Wv };

    // preload chunk 0 into buf 0
    {
        float4 v = *(const float4*)&xrow[xk4];
        xs[0][xk4 + 0][xr] = v.x;
        xs[0][xk4 + 1][xr] = v.y;
        xs[0][xk4 + 2][xr] = v.z;
        xs[0][xk4 + 3][xr] = v.w;
        #pragma unroll
        for (int i = 0; i < 2; i++)
            #pragma unroll
            for (int j = 0; j < 3; j++)
                *(float4*)&ws[0][wk + 8 * i][64 * j + wc4] =
                    *(const float4*)&Wm[j][(size_t)(wk + 8 * i) * NH + wc4];
    }
    __syncthreads();

    int buf = 0;
    for (int kb = 0; kb < ND; kb += 16) {
        const bool has_next = (kb + 16 < ND);
        float4 px, pw[2][3];
        if (has_next) {   // LDG next chunk into registers (latency overlapped)
            px = *(const float4*)&xrow[kb + 16 + xk4];
            #pragma unroll
            for (int i = 0; i < 2; i++)
                #pragma unroll
                for (int j = 0; j < 3; j++)
                    pw[i][j] = *(const float4*)&Wm[j][(size_t)(kb + 16 + wk + 8 * i) * NH + wc4];
        }
        #pragma unroll
        for (int kk = 0; kk < 16; kk++) {
            float4 a = *(const float4*)&xs[buf][kk][ty * 4];
            ulonglong2 wA = *(const ulonglong2*)&ws[buf][kk][tx * 12];
            ulonglong2 wB = *(const ulonglong2*)&ws[buf][kk][tx * 12 + 4];
            ulonglong2 wC = *(const ulonglong2*)&ws[buf][kk][tx * 12 + 8];
            ull ap[4] = { pack2s(a.x), pack2s(a.y), pack2s(a.z), pack2s(a.w) };
            ull wp[6] = { wA.x, wA.y, wB.x, wB.y, wC.x, wC.y };
            #pragma unroll
            for (int i = 0; i < 4; i++)
                #pragma unroll
                for (int j = 0; j < 6; j++)
                    fma2(acc[i][j], ap[i], wp[j]);
        }
        if (has_next) {
            const int nb = buf ^ 1;
            xs[nb][xk4 + 0][xr] = px.x;
            xs[nb][xk4 + 1][xr] = px.y;
            xs[nb][xk4 + 2][xr] = px.z;
            xs[nb][xk4 + 3][xr] = px.w;
            #pragma unroll
            for (int i = 0; i < 2; i++)
                #pragma unroll
                for (int j = 0; j < 3; j++)
                    *(float4*)&ws[nb][wk + 8 * i][64 * j + wc4] = pw[i][j];
        }
        __syncthreads();
        buf ^= 1;
    }

    // epilogue: cols < 128 -> transposed q/k; cols >= 128 -> row-major v
    #pragma unroll
    for (int jp = 0; jp < 6; jp++) {
        const int c0 = tx * 12 + 2 * jp;
        float2 u0 = unpack2(acc[0][jp]), u1 = unpack2(acc[1][jp]);
        float2 u2 = unpack2(acc[2][jp]), u3 = unpack2(acc[3][jp]);
        if (c0 < 128) {
            float* __restrict__ OT = (c0 < 64) ? g_qT : g_kT;
            const int lc = c0 & 63;
            const size_t base = (size_t)(b * NH + lc) * NT + t0 + ty * 4;
            *(float4*)&OT[base]      = make_float4(u0.x, u1.x, u2.x, u3.x);
            *(float4*)&OT[base + NT] = make_float4(u0.y, u1.y, u2.y, u3.y);
        } else {
            const int lc = c0 - 128;
            const size_t r0 = ((size_t)b * NT + t0 + ty * 4) * NH + lc;
            *(float2*)&g_v[r0]          = u0;
            *(float2*)&g_v[r0 + NH]     = u1;
            *(float2*)&g_v[r0 + 2 * NH] = u2;
            *(float2*)&g_v[r0 + 3 * NH] = u3;
        }
    }
}

// ---------------------------------------------------------------------------
// Flash-attention partials: BQ=64, BK=64, 128 threads, split-K via z.
// (unchanged from round 8)
// ---------------------------------------------------------------------------
#define PSTRIDE 70
#define OFF_QT 0                       // QsT [64h][68]
#define OFF_KT (64 * 68)               // KsT [64h][68]
#define OFF_VS (OFF_KT + 64 * 68)      // Vs  [64k][68]
#define OFF_PS (OFF_VS + 64 * 68)      // Ps  [64r][70]
#define OFF_CR (OFF_PS + 64 * PSTRIDE) // corr[64]
#define OFF_OS OFF_KT                  // Os  [64r][68] overlays KsT
#define SM_FLOATS (OFF_CR + 64)
#define SM_BYTES (SM_FLOATS * 4)

__global__ void attn_part(const int* __restrict__ valid_lens)
{
    extern __shared__ float sm[];
    const int b  = blockIdx.y;
    const int q0 = blockIdx.x * 64;
    const int s  = blockIdx.z;
    int L = valid_lens[b];
    if (L < 0) L = 0;
    if (L > NT) L = NT;
    if (q0 >= L) return;

    const int tid = threadIdx.x;
    const int kg  = tid & 15;          // S: 16 key groups *4
    const int rg  = tid >> 4;          // S: 8 row groups *8
    const int hg  = tid & 7;           // PV: 8 h groups *8
    const int rg2 = (tid >> 3) & 7;    // PV: 8 row groups *8
    const int ks  = tid >> 6;          // PV: key half (32 keys each)

    const int kend = (q0 + 64 < L) ? (q0 + 64) : L;
    const int C  = (((kend + SPL - 1) / SPL) + 63) & ~63;
    const int jb = s * C;
    const int je = (jb + C < kend) ? (jb + C) : kend;

    if (jb >= je) {  // empty split: neutral partials
        const float4 z4 = make_float4(0.f, 0.f, 0.f, 0.f);
        #pragma unroll
        for (int i = 0; i < 8; i++) {
            int idx = tid + 128 * i;
            int row = idx >> 4, h4 = (idx & 15) * 4;
            *(float4*)&g_po[((size_t)(b * NT + q0 + row) * SPL + s) * NH + h4] = z4;
        }
        if (tid < 64) {
            g_pm[(size_t)(b * NT + q0 + tid) * SPL + s] = -1e30f;
            g_pl[(size_t)(b * NT + q0 + tid) * SPL + s] = 0.f;
        }
        return;
    }

    // load QsT
    #pragma unroll
    for (int i = 0; i < 8; i++) {
        int idx = tid + 128 * i;
        int h = idx >> 4, r4 = (idx & 15) * 4;
        *(float4*)&sm[OFF_QT + h * 68 + r4] =
            *(const float4*)&g_qT[(size_t)(b * NH + h) * NT + q0 + r4];
    }

    float m[8], l[8];
    #pragma unroll
    for (int i = 0; i < 8; i++) { m[i] = -1e30f; l[i] = 0.f; }
    ull o[8][4];
    #pragma unroll
    for (int i = 0; i < 8; i++)
        #pragma unroll
        for (int p = 0; p < 4; p++) o[i][p] = 0ull;

    for (int j0 = jb; j0 < je; j0 += 64) {
        __syncthreads();
        #pragma unroll
        for (int i = 0; i < 8; i++) {
            int idx = tid + 128 * i;
            int h = idx >> 4, k4 = (idx & 15) * 4;
            *(float4*)&sm[OFF_KT + h * 68 + k4] =
                *(const float4*)&g_kT[(size_t)(b * NH + h) * NT + j0 + k4];
            int key = idx >> 4, h4 = (idx & 15) * 4;
            *(float4*)&sm[OFF_VS + key * 68 + h4] =
                *(const float4*)&g_v[((size_t)b * NT + j0 + key) * NH + h4];
        }
        __syncthreads();

        // ---- S = Q K^T : 8 rows x 4 keys per thread
        ull sacc[8][2];
        #pragma unroll
        for (int i = 0; i < 8; i++) { sacc[i][0] = 0ull; sacc[i][1] = 0ull; }

        #pragma unroll 8
        for (int h = 0; h < NH; h++) {
            float4 qa = *(const float4*)&sm[OFF_QT + h * 68 + rg * 8];
            float4 qb = *(const float4*)&sm[OFF_QT + h * 68 + rg * 8 + 4];
            ulonglong2 kk2 = *(const ulonglong2*)&sm[OFF_KT + h * 68 + kg * 4];
            ull qq[8] = { pack2s(qa.x), pack2s(qa.y), pack2s(qa.z), pack2s(qa.w),
                          pack2s(qb.x), pack2s(qb.y), pack2s(qb.z), pack2s(qb.w) };
            #pragma unroll
            for (int i = 0; i < 8; i++) {
                fma2(sacc[i][0], qq[i], kk2.x);
                fma2(sacc[i][1], qq[i], kk2.y);
            }
        }

        // ---- softmax per row
        #pragma unroll
        for (int i = 0; i < 8; i++) {
            const int q = q0 + rg * 8 + i;
            float2 u0 = unpack2(sacc[i][0]), u1 = unpack2(sacc[i][1]);
            float sv[4] = { u0.x, u0.y, u1.x, u1.y };
            #pragma unroll
            for (int c = 0; c < 4; c++) {
                int key = j0 + kg * 4 + c;
                bool valid = (key <= q) && (key < L);
                sv[c] = valid ? sv[c] * 0.125f : -1e30f;
            }
            float tm = fmaxf(fmaxf(sv[0], sv[1]), fmaxf(sv[2], sv[3]));
            #pragma unroll
            for (int off = 1; off < 16; off <<= 1)
                tm = fmaxf(tm, __shfl_xor_sync(0xffffffffu, tm, off));
            const float mn = fmaxf(m[i], tm);
            const float corr = __expf(m[i] - mn);
            float pj[4], psum = 0.f;
            #pragma unroll
            for (int c = 0; c < 4; c++) {
                pj[c] = (sv[c] > -1e29f) ? __expf(sv[c] - mn) : 0.f;
                psum += pj[c];
            }
            #pragma unroll
            for (int off = 1; off < 16; off <<= 1)
                psum += __shfl_xor_sync(0xffffffffu, psum, off);
            l[i] = l[i] * corr + psum;
            m[i] = mn;
            const int rb = OFF_PS + (rg * 8 + i) * PSTRIDE + kg * 4;
            *(float2*)&sm[rb]     = make_float2(pj[0], pj[1]);
            *(float2*)&sm[rb + 2] = make_float2(pj[2], pj[3]);
            if (kg == 0) sm[OFF_CR + rg * 8 + i] = corr;
        }
        __syncthreads();

        // ---- rescale O, then O += P V over this thread's 32-key half
        #pragma unroll
        for (int i = 0; i < 8; i++) {
            ull c2 = pack2s(sm[OFF_CR + rg2 * 8 + i]);
            #pragma unroll
            for (int p = 0; p < 4; p++) mul2(o[i][p], c2);
        }
        for (int k = 0; k < 32; k++) {
            const int key = ks * 32 + k;
            ulonglong2 va = *(const ulonglong2*)&sm[OFF_VS + key * 68 + hg * 8];
            ulonglong2 vb = *(const ulonglong2*)&sm[OFF_VS + key * 68 + hg * 8 + 4];
            ull vv[4] = { va.x, va.y, vb.x, vb.y };
            #pragma unroll
            for (int i = 0; i < 8; i++) {
                ull pp = pack2s(sm[OFF_PS + (rg2 * 8 + i) * PSTRIDE + key]);
                #pragma unroll
                for (int p = 0; p < 4; p++)
                    fma2(o[i][p], pp, vv[p]);
            }
        }
    }

    // write pm/pl (S mapping)
    if (kg == 0) {
        #pragma unroll
        for (int i = 0; i < 8; i++) {
            const size_t pi = (size_t)(b * NT + q0 + rg * 8 + i) * SPL + s;
            g_pm[pi] = m[i];
            g_pl[pi] = l[i];
        }
    }

    // merge ks halves, write po
    __syncthreads();
    if (ks == 1) {
        #pragma unroll
        for (int i = 0; i < 8; i++) {
            float2 u0 = unpack2(o[i][0]), u1 = unpack2(o[i][1]);
            float2 u2 = unpack2(o[i][2]), u3 = unpack2(o[i][3]);
            *(float4*)&sm[OFF_OS + (rg2 * 8 + i) * 68 + hg * 8] =
                make_float4(u0.x, u0.y, u1.x, u1.y);
            *(float4*)&sm[OFF_OS + (rg2 * 8 + i) * 68 + hg * 8 + 4] =
                make_float4(u2.x, u2.y, u3.x, u3.y);
        }
    }
    __syncthreads();
    if (ks == 0) {
        #pragma unroll
        for (int i = 0; i < 8; i++) {
            float2 u0 = unpack2(o[i][0]), u1 = unpack2(o[i][1]);
            float2 u2 = unpack2(o[i][2]), u3 = unpack2(o[i][3]);
            float4 s0 = *(const float4*)&sm[OFF_OS + (rg2 * 8 + i) * 68 + hg * 8];
            float4 s1 = *(const float4*)&sm[OFF_OS + (rg2 * 8 + i) * 68 + hg * 8 + 4];
            const size_t po = ((size_t)(b * NT + q0 + rg2 * 8 + i) * SPL + s) * NH + hg * 8;
            *(float4*)&g_po[po] =
                make_float4(u0.x + s0.x, u0.y + s0.y, u1.x + s0.z, u1.y + s0.w);
            *(float4*)&g_po[po + 4] =
                make_float4(u2.x + s1.x, u2.y + s1.y, u3.x + s1.z, u3.y + s1.w);
        }
    }
}

// ---------------------------------------------------------------------------
// Combine split-K partials.
// ---------------------------------------------------------------------------
__global__ __launch_bounds__(128) void attn_combine(
    const int* __restrict__ valid_lens, float* __restrict__ out)
{
    const int b   = blockIdx.y;
    const int tid = threadIdx.x;
    const int row = tid >> 3;
    const int t8  = tid & 7;
    const int q   = blockIdx.x * 16 + row;
    int L = valid_lens[b];
    if (L < 0) L = 0;
    if (L > NT) L = NT;

    const size_t base0 = (size_t)(b * NT + q) * SPL;
    float ms[SPL], mstar = -1e30f;
    #pragma unroll
    for (int s = 0; s < SPL; s++) {
        ms[s] = g_pm[base0 + s];
        mstar = fmaxf(mstar, ms[s]);
    }
    float l = 0.f;
    float4 oA = make_float4(0.f, 0.f, 0.f, 0.f);
    float4 oB = make_float4(0.f, 0.f, 0.f, 0.f);
    #pragma unroll
    for (int s = 0; s < SPL; s++) {
        const float w = (ms[s] > -1e29f) ? __expf(ms[s] - mstar) : 0.f;
        l += g_pl[base0 + s] * w;
        float4 a = *(const float4*)&g_po[(base0 + s) * NH + t8 * 4];
        float4 c = *(const float4*)&g_po[(base0 + s) * NH + 32 + t8 * 4];
        oA.x += a.x * w; oA.y += a.y * w; oA.z += a.z * w; oA.w += a.w * w;
        oB.x += c.x * w; oB.y += c.y * w; oB.z += c.z * w; oB.w += c.w * w;
    }
    const float inv = (q < L && l > 0.f) ? (1.f / l) : 0.f;
    const size_t ob = ((size_t)b * NT + q) * NH;
    *(float4*)&out[ob + t8 * 4] =
        make_float4(oA.x * inv, oA.y * inv, oA.z * inv, oA.w * inv);
    *(float4*)&out[ob + 32 + t8 * 4] =
        make_float4(oB.x * inv, oB.y * inv, oB.z * inv, oB.w * inv);
}

extern "C" void kernel_launch(void* const* d_in, const int* in_sizes, int n_in,
                              void* d_out, int out_size)
{
    const float* x  = (const float*)d_in[0];
    const float* Wq = (const float*)d_in[1];
    const float* Wk = (const float*)d_in[2];
    const float* Wv = (const float*)d_in[3];
    const int*   vl = (const int*)d_in[4];
    float* out = (float*)d_out;

    cudaFuncSetAttribute(attn_part, cudaFuncAttributeMaxDynamicSharedMemorySize, SM_BYTES);

    proj_kernel<<<dim3(NT / 32, NB), 128>>>(x, Wq, Wk, Wv, vl);
    attn_part<<<dim3(NT / 64, NB, SPL), 128, SM_BYTES>>>(vl);
    attn_combine<<<dim3(NT / 16, NB), 128>>>(vl, out);
}

// round 11
// speedup vs baseline: 1.9456x; 1.4864x over previous
#include <cuda_runtime.h>
#include <cstdint>

#define NB 8
#define NT 2048
#define ND 1024
#define NH 64
#define SPL 2

typedef unsigned long long ull;

// ---------------- f32x2 helpers (attn) ----------------
__device__ __forceinline__ ull pack2s(float v) {
    ull r; asm("mov.b64 %0, {%1, %2};" : "=l"(r) : "f"(v), "f"(v)); return r;
}
__device__ __forceinline__ void fma2(ull& d, ull a, ull b) {
    asm("fma.rn.f32x2 %0, %1, %2, %0;" : "+l"(d) : "l"(a), "l"(b));
}
__device__ __forceinline__ void mul2(ull& d, ull a) {
    asm("mul.rn.f32x2 %0, %0, %1;" : "+l"(d) : "l"(a));
}
__device__ __forceinline__ float2 unpack2(ull v) {
    float2 r; asm("mov.b64 {%0, %1}, %2;" : "=f"(r.x), "=f"(r.y) : "l"(v)); return r;
}

__device__ __forceinline__ uint32_t f2tf32(float f) {
    uint32_t u; asm("cvt.rna.tf32.f32 %0, %1;" : "=r"(u) : "f"(f)); return u;
}

// Q,K transposed [b][h][t]; V row-major [b][t][h]; split-K partials.
__device__ float g_qT[NB * NH * NT];
__device__ float g_kT[NB * NH * NT];
__device__ float g_v [NB * NT * NH];
__device__ float g_po[(size_t)NB * NT * SPL * NH];
__device__ float g_pm[NB * NT * SPL];
__device__ float g_pl[NB * NT * SPL];

// ---------------------------------------------------------------------------
// Projection via mma.sync tf32 (m16n8k8). Block: 256 thr / 8 warps.
// Tile: 64 rows x 192 cols (q|k|v). Warp tile 32x48. BK=32, double-buffered.
// A smem [64r][36] (tf32 bits), B smem [32k][196] (tf32 bits).
// ---------------------------------------------------------------------------
#define PJ_AS 2304                 // 64*36 floats
#define PJ_BS 6272                 // 32*196 floats
#define PJ_BUF (PJ_AS + PJ_BS)     // 8576 floats
#define PJ_SMEM_BYTES (2 * PJ_BUF * 4)   // 68608 B

__global__ __launch_bounds__(256) void proj_mma(
    const float* __restrict__ x, const float* __restrict__ Wq,
    const float* __restrict__ Wk, const float* __restrict__ Wv,
    const int* __restrict__ valid_lens)
{
    extern __shared__ float pjs[];
    const int b  = blockIdx.y;
    const int t0 = blockIdx.x * 64;
    int L = valid_lens[b];
    if (L < 0) L = 0;
    if (L > NT) L = NT;
    if (t0 >= L) return;

    const int tid  = threadIdx.x;
    const int lane = tid & 31;
    const int wid  = tid >> 5;
    const int g    = lane >> 2;   // group id (0..7)
    const int t    = lane & 3;    // thread-in-group
    const int mrow = (wid & 1) * 32;
    const int ncol = (wid >> 1) * 48;

    const float* Wm[3] = { Wq, Wk, Wv };

    // loader indices
    const int ar  = tid >> 3;             // A row 0..31 (+32)
    const int ak4 = (tid & 7) * 4;        // A k 0,4,..28

    float d[2][6][4];
    #pragma unroll
    for (int mt = 0; mt < 2; mt++)
        #pragma unroll
        for (int nt = 0; nt < 6; nt++)
            #pragma unroll
            for (int e = 0; e < 4; e++) d[mt][nt][e] = 0.f;

    // ---- preload chunk 0 into buffer 0
    {
        float* As = pjs;
        float* Bs = pjs + PJ_AS;
        #pragma unroll
        for (int i = 0; i < 2; i++) {
            int r = ar + 32 * i;
            float4 v = *(const float4*)&x[((size_t)b * NT + t0 + r) * ND + ak4];
            As[r * 36 + ak4 + 0] = __uint_as_float(f2tf32(v.x));
            As[r * 36 + ak4 + 1] = __uint_as_float(f2tf32(v.y));
            As[r * 36 + ak4 + 2] = __uint_as_float(f2tf32(v.z));
            As[r * 36 + ak4 + 3] = __uint_as_float(f2tf32(v.w));
        }
        #pragma unroll
        for (int i = 0; i < 6; i++) {
            int idx = tid + 256 * i;       // 0..1535
            int k   = idx / 48;
            int c4  = (idx % 48) * 4;      // 0..188
            int j   = c4 >> 6;
            int hh  = c4 & 63;
            float4 v = *(const float4*)&Wm[j][(size_t)k * NH + hh];
            Bs[k * 196 + c4 + 0] = __uint_as_float(f2tf32(v.x));
            Bs[k * 196 + c4 + 1] = __uint_as_float(f2tf32(v.y));
            Bs[k * 196 + c4 + 2] = __uint_as_float(f2tf32(v.z));
            Bs[k * 196 + c4 + 3] = __uint_as_float(f2tf32(v.w));
        }
    }
    __syncthreads();

    int buf = 0;
    for (int c = 0; c < 32; c++) {
        const int kb = c * 32;
        const bool has_next = (c < 31);
        float4 pa[2], pb[6];
        if (has_next) {
            #pragma unroll
            for (int i = 0; i < 2; i++) {
                int r = ar + 32 * i;
                pa[i] = *(const float4*)&x[((size_t)b * NT + t0 + r) * ND + kb + 32 + ak4];
            }
            #pragma unroll
            for (int i = 0; i < 6; i++) {
                int idx = tid + 256 * i;
                int k   = idx / 48;
                int c4  = (idx % 48) * 4;
                int j   = c4 >> 6;
                int hh  = c4 & 63;
                pb[i] = *(const float4*)&Wm[j][(size_t)(kb + 32 + k) * NH + hh];
            }
        }

        const float* As = pjs + buf * PJ_BUF;
        const float* Bs = As + PJ_AS;
        #pragma unroll
        for (int k8 = 0; k8 < 4; k8++) {
            const int kc = k8 * 8 + t;
            uint32_t afr[2][4];
            #pragma unroll
            for (int mt = 0; mt < 2; mt++) {
                const int r0 = mrow + mt * 16 + g;
                afr[mt][0] = __float_as_uint(As[r0 * 36 + kc]);
                afr[mt][1] = __float_as_uint(As[(r0 + 8) * 36 + kc]);
                afr[mt][2] = __float_as_uint(As[r0 * 36 + kc + 4]);
                afr[mt][3] = __float_as_uint(As[(r0 + 8) * 36 + kc + 4]);
            }
            uint32_t bfr[6][2];
            #pragma unroll
            for (int nt = 0; nt < 6; nt++) {
                const int n = ncol + nt * 8 + g;
                bfr[nt][0] = __float_as_uint(Bs[kc * 196 + n]);
                bfr[nt][1] = __float_as_uint(Bs[(kc + 4) * 196 + n]);
            }
            #pragma unroll
            for (int mt = 0; mt < 2; mt++)
                #pragma unroll
                for (int nt = 0; nt < 6; nt++)
                    asm volatile(
                        "mma.sync.aligned.m16n8k8.row.col.f32.tf32.tf32.f32 "
                        "{%0,%1,%2,%3}, {%4,%5,%6,%7}, {%8,%9}, {%0,%1,%2,%3};"
                        : "+f"(d[mt][nt][0]), "+f"(d[mt][nt][1]),
                          "+f"(d[mt][nt][2]), "+f"(d[mt][nt][3])
                        : "r"(afr[mt][0]), "r"(afr[mt][1]), "r"(afr[mt][2]), "r"(afr[mt][3]),
                          "r"(bfr[nt][0]), "r"(bfr[nt][1]));
        }

        if (has_next) {
            float* As2 = pjs + (buf ^ 1) * PJ_BUF;
            float* Bs2 = As2 + PJ_AS;
            #pragma unroll
            for (int i = 0; i < 2; i++) {
                int r = ar + 32 * i;
                As2[r * 36 + ak4 + 0] = __uint_as_float(f2tf32(pa[i].x));
                As2[r * 36 + ak4 + 1] = __uint_as_float(f2tf32(pa[i].y));
                As2[r * 36 + ak4 + 2] = __uint_as_float(f2tf32(pa[i].z));
                As2[r * 36 + ak4 + 3] = __uint_as_float(f2tf32(pa[i].w));
            }
            #pragma unroll
            for (int i = 0; i < 6; i++) {
                int idx = tid + 256 * i;
                int k   = idx / 48;
                int c4  = (idx % 48) * 4;
                Bs2[k * 196 + c4 + 0] = __uint_as_float(f2tf32(pb[i].x));
                Bs2[k * 196 + c4 + 1] = __uint_as_float(f2tf32(pb[i].y));
                Bs2[k * 196 + c4 + 2] = __uint_as_float(f2tf32(pb[i].z));
                Bs2[k * 196 + c4 + 3] = __uint_as_float(f2tf32(pb[i].w));
            }
        }
        __syncthreads();
        buf ^= 1;
    }

    // ---- epilogue: stage D into smem [col 192][row 64] stride 68, then write
    float* sm2 = pjs;   // 192*68 = 13056 <= 17152 floats
    #pragma unroll
    for (int mt = 0; mt < 2; mt++)
        #pragma unroll
        for (int nt = 0; nt < 6; nt++)
            #pragma unroll
            for (int e = 0; e < 4; e++) {
                const int r = mrow + mt * 16 + g + ((e >= 2) ? 8 : 0);
                const int cc = ncol + nt * 8 + 2 * t + (e & 1);
                sm2[cc * 68 + r] = d[mt][nt][e];
            }
    __syncthreads();

    // q/k transposed stores: cols 0..127
    #pragma unroll
    for (int i = 0; i < 8; i++) {
        int idx = tid + 256 * i;          // 0..2047
        int cc  = idx >> 4;               // 0..127
        int r4  = (idx & 15) * 4;
        float4 v = *(const float4*)&sm2[cc * 68 + r4];
        float* __restrict__ OT = (cc < 64) ? g_qT : g_kT;
        *(float4*)&OT[(size_t)(b * NH + (cc & 63)) * NT + t0 + r4] = v;
    }
    // v row-major stores: cols 128..191
    #pragma unroll
    for (int i = 0; i < 4; i++) {
        int idx = tid + 256 * i;          // 0..1023
        int r   = idx >> 4;               // 0..63
        int c4  = (idx & 15) * 4;         // 0..60
        float4 v;
        v.x = sm2[(128 + c4 + 0) * 68 + r];
        v.y = sm2[(128 + c4 + 1) * 68 + r];
        v.z = sm2[(128 + c4 + 2) * 68 + r];
        v.w = sm2[(128 + c4 + 3) * 68 + r];
        *(float4*)&g_v[((size_t)b * NT + t0 + r) * NH + c4] = v;
    }
}

// ---------------------------------------------------------------------------
// Flash-attention partials: BQ=64, BK=128, 128 threads, split-K via z.
// (round-4 measured-best version, verbatim)
// ---------------------------------------------------------------------------
#define OFF_QT 0
#define OFF_KT 4352
#define OFF_VS 12800
#define OFF_PS 21504
#define OFF_CR 29952
#define OFF_OS OFF_KT
#define SM_FLOATS 30016
#define SM_BYTES (SM_FLOATS * 4)

__global__ void attn_part(const int* __restrict__ valid_lens)
{
    extern __shared__ float sm[];
    const int b  = blockIdx.y;
    const int q0 = blockIdx.x * 64;
    const int s  = blockIdx.z;
    int L = valid_lens[b];
    if (L < 0) L = 0;
    if (L > NT) L = NT;
    if (q0 >= L) return;

    const int tid = threadIdx.x;
    const int kg  = tid & 15;
    const int rg  = tid >> 4;
    const int hg  = tid & 7;
    const int rg2 = (tid >> 3) & 7;
    const int ks  = tid >> 6;

    const int kend = (q0 + 64 < L) ? (q0 + 64) : L;
    const int C = (((kend + SPL - 1) / SPL) + 127) & ~127;
    const int jb = s * C;
    const int je = (jb + C < kend) ? (jb + C) : kend;

    if (jb >= je) {
        const float4 z4 = make_float4(0.f, 0.f, 0.f, 0.f);
        #pragma unroll
        for (int i = 0; i < 8; i++) {
            int idx = tid + 128 * i;
            int row = idx >> 4, h4 = (idx & 15) * 4;
            *(float4*)&g_po[((size_t)(b * NT + q0 + row) * SPL + s) * NH + h4] = z4;
        }
        if (tid < 64) {
            g_pm[(size_t)(b * NT + q0 + tid) * SPL + s] = -1e30f;
            g_pl[(size_t)(b * NT + q0 + tid) * SPL + s] = 0.f;
        }
        return;
    }

    #pragma unroll
    for (int i = 0; i < 8; i++) {
        int idx = tid + 128 * i;
        int h = idx >> 4, r4 = (idx & 15) * 4;
        *(float4*)&sm[OFF_QT + h * 68 + r4] =
            *(const float4*)&g_qT[(size_t)(b * NH + h) * NT + q0 + r4];
    }

    float m[8], l[8];
    #pragma unroll
    for (int i = 0; i < 8; i++) { m[i] = -1e30f; l[i] = 0.f; }
    ull o[8][4];
    #pragma unroll
    for (int i = 0; i < 8; i++)
        #pragma unroll
        for (int p = 0; p < 4; p++) o[i][p] = 0ull;

    for (int j0 = jb; j0 < je; j0 += 128) {
        __syncthreads();
        #pragma unroll
        for (int i = 0; i < 16; i++) {
            int idx = tid + 128 * i;
            int h = idx >> 5, k4 = (idx & 31) * 4;
            *(float4*)&sm[OFF_KT + h * 132 + k4] =
                *(const float4*)&g_kT[(size_t)(b * NH + h) * NT + j0 + k4];
            int key = idx >> 4, h4 = (idx & 15) * 4;
            *(float4*)&sm[OFF_VS + key * 68 + h4] =
                *(const float4*)&g_v[((size_t)b * NT + j0 + key) * NH + h4];
        }
        __syncthreads();

        ull sacc[8][4];
        #pragma unroll
        for (int i = 0; i < 8; i++)
            #pragma unroll
            for (int p = 0; p < 4; p++) sacc[i][p] = 0ull;

        for (int h = 0; h < NH; h++) {
            float4 qa = *(const float4*)&sm[OFF_QT + h * 68 + rg * 8];
            float4 qb = *(const float4*)&sm[OFF_QT + h * 68 + rg * 8 + 4];
            ulonglong2 ka = *(const ulonglong2*)&sm[OFF_KT + h * 132 + kg * 8];
            ulonglong2 kb2 = *(const ulonglong2*)&sm[OFF_KT + h * 132 + kg * 8 + 4];
            ull qq[8] = { pack2s(qa.x), pack2s(qa.y), pack2s(qa.z), pack2s(qa.w),
                          pack2s(qb.x), pack2s(qb.y), pack2s(qb.z), pack2s(qb.w) };
            ull kk[4] = { ka.x, ka.y, kb2.x, kb2.y };
            #pragma unroll
            for (int i = 0; i < 8; i++)
                #pragma unroll
                for (int p = 0; p < 4; p++)
                    fma2(sacc[i][p], qq[i], kk[p]);
        }

        #pragma unroll
        for (int i = 0; i < 8; i++) {
            const int q = q0 + rg * 8 + i;
            float sv[8];
            #pragma unroll
            for (int p = 0; p < 4; p++) {
                float2 u = unpack2(sacc[i][p]);
                sv[2 * p] = u.x; sv[2 * p + 1] = u.y;
            }
            #pragma unroll
            for (int c = 0; c < 8; c++) {
                int key = j0 + kg * 8 + c;
                bool valid = (key <= q) && (key < L);
                sv[c] = valid ? sv[c] * 0.125f : -1e30f;
            }
            float tm = sv[0];
            #pragma unroll
            for (int c = 1; c < 8; c++) tm = fmaxf(tm, sv[c]);
            #pragma unroll
            for (int off = 1; off < 16; off <<= 1)
                tm = fmaxf(tm, __shfl_xor_sync(0xffffffffu, tm, off));
            const float mn = fmaxf(m[i], tm);
            const float corr = __expf(m[i] - mn);
            float pj[8], psum = 0.f;
            #pragma unroll
            for (int c = 0; c < 8; c++) {
                pj[c] = (sv[c] > -1e29f) ? __expf(sv[c] - mn) : 0.f;
                psum += pj[c];
            }
            #pragma unroll
            for (int off = 1; off < 16; off <<= 1)
                psum += __shfl_xor_sync(0xffffffffu, psum, off);
            l[i] = l[i] * corr + psum;
            m[i] = mn;
            *(float4*)&sm[OFF_PS + (rg * 8 + i) * 132 + kg * 8] =
                make_float4(pj[0], pj[1], pj[2], pj[3]);
            *(float4*)&sm[OFF_PS + (rg * 8 + i) * 132 + kg * 8 + 4] =
                make_float4(pj[4], pj[5], pj[6], pj[7]);
            if (kg == 0) sm[OFF_CR + rg * 8 + i] = corr;
        }
        __syncthreads();

        #pragma unroll
        for (int i = 0; i < 8; i++) {
            ull c2 = pack2s(sm[OFF_CR + rg2 * 8 + i]);
            #pragma unroll
            for (int p = 0; p < 4; p++) mul2(o[i][p], c2);
        }
        for (int k = 0; k < 64; k++) {
            const int key = ks * 64 + k;
            ulonglong2 va = *(const ulonglong2*)&sm[OFF_VS + key * 68 + hg * 8];
            ulonglong2 vb = *(const ulonglong2*)&sm[OFF_VS + key * 68 + hg * 8 + 4];
            ull vv[4] = { va.x, va.y, vb.x, vb.y };
            #pragma unroll
            for (int i = 0; i < 8; i++) {
                ull pp = pack2s(sm[OFF_PS + (rg2 * 8 + i) * 132 + key]);
                #pragma unroll
                for (int p = 0; p < 4; p++)
                    fma2(o[i][p], pp, vv[p]);
            }
        }
    }

    if (kg == 0) {
        #pragma unroll
        for (int i = 0; i < 8; i++) {
            const size_t pi = (size_t)(b * NT + q0 + rg * 8 + i) * SPL + s;
            g_pm[pi] = m[i];
            g_pl[pi] = l[i];
        }
    }

    __syncthreads();
    if (ks == 1) {
        #pragma unroll
        for (int i = 0; i < 8; i++) {
            float2 u0 = unpack2(o[i][0]), u1 = unpack2(o[i][1]);
            float2 u2 = unpack2(o[i][2]), u3 = unpack2(o[i][3]);
            *(float4*)&sm[OFF_OS + (rg2 * 8 + i) * 68 + hg * 8] =
                make_float4(u0.x, u0.y, u1.x, u1.y);
            *(float4*)&sm[OFF_OS + (rg2 * 8 + i) * 68 + hg * 8 + 4] =
                make_float4(u2.x, u2.y, u3.x, u3.y);
        }
    }
    __syncthreads();
    if (ks == 0) {
        #pragma unroll
        for (int i = 0; i < 8; i++) {
            float2 u0 = unpack2(o[i][0]), u1 = unpack2(o[i][1]);
            float2 u2 = unpack2(o[i][2]), u3 = unpack2(o[i][3]);
            float4 s0 = *(const float4*)&sm[OFF_OS + (rg2 * 8 + i) * 68 + hg * 8];
            float4 s1 = *(const float4*)&sm[OFF_OS + (rg2 * 8 + i) * 68 + hg * 8 + 4];
            const size_t po = ((size_t)(b * NT + q0 + rg2 * 8 + i) * SPL + s) * NH + hg * 8;
            *(float4*)&g_po[po] =
                make_float4(u0.x + s0.x, u0.y + s0.y, u1.x + s0.z, u1.y + s0.w);
            *(float4*)&g_po[po + 4] =
                make_float4(u2.x + s1.x, u2.y + s1.y, u3.x + s1.z, u3.y + s1.w);
        }
    }
}

__global__ __launch_bounds__(128) void attn_combine(
    const int* __restrict__ valid_lens, float* __restrict__ out)
{
    const int b   = blockIdx.y;
    const int tid = threadIdx.x;
    const int row = tid >> 3;
    const int t8  = tid & 7;
    const int q   = blockIdx.x * 16 + row;
    int L = valid_lens[b];
    if (L < 0) L = 0;
    if (L > NT) L = NT;

    const size_t base0 = (size_t)(b * NT + q) * SPL;
    float ms[SPL], mstar = -1e30f;
    #pragma unroll
    for (int s = 0; s < SPL; s++) {
        ms[s] = g_pm[base0 + s];
        mstar = fmaxf(mstar, ms[s]);
    }
    float l = 0.f;
    float4 oA = make_float4(0.f, 0.f, 0.f, 0.f);
    float4 oB = make_float4(0.f, 0.f, 0.f, 0.f);
    #pragma unroll
    for (int s = 0; s < SPL; s++) {
        const float w = (ms[s] > -1e29f) ? __expf(ms[s] - mstar) : 0.f;
        l += g_pl[base0 + s] * w;
        float4 a = *(const float4*)&g_po[(base0 + s) * NH + t8 * 4];
        float4 c = *(const float4*)&g_po[(base0 + s) * NH + 32 + t8 * 4];
        oA.x += a.x * w; oA.y += a.y * w; oA.z += a.z * w; oA.w += a.w * w;
        oB.x += c.x * w; oB.y += c.y * w; oB.z += c.z * w; oB.w += c.w * w;
    }
    const float inv = (q < L && l > 0.f) ? (1.f / l) : 0.f;
    const size_t ob = ((size_t)b * NT + q) * NH;
    *(float4*)&out[ob + t8 * 4] =
        make_float4(oA.x * inv, oA.y * inv, oA.z * inv, oA.w * inv);
    *(float4*)&out[ob + 32 + t8 * 4] =
        make_float4(oB.x * inv, oB.y * inv, oB.z * inv, oB.w * inv);
}

extern "C" void kernel_launch(void* const* d_in, const int* in_sizes, int n_in,
                              void* d_out, int out_size)
{
    const float* x  = (const float*)d_in[0];
    const float* Wq = (const float*)d_in[1];
    const float* Wk = (const float*)d_in[2];
    const float* Wv = (const float*)d_in[3];
    const int*   vl = (const int*)d_in[4];
    float* out = (float*)d_out;

    cudaFuncSetAttribute(proj_mma, cudaFuncAttributeMaxDynamicSharedMemorySize, PJ_SMEM_BYTES);
    cudaFuncSetAttribute(attn_part, cudaFuncAttributeMaxDynamicSharedMemorySize, SM_BYTES);

    proj_mma<<<dim3(NT / 64, NB), 256, PJ_SMEM_BYTES>>>(x, Wq, Wk, Wv, vl);
    attn_part<<<dim3(NT / 64, NB, SPL), 128, SM_BYTES>>>(vl);
    attn_combine<<<dim3(NT / 16, NB), 128>>>(vl, out);
}

// round 12
// speedup vs baseline: 2.5978x; 1.3352x over previous
#include <cuda_runtime.h>
#include <cstdint>

#define NB 8
#define NT 2048
#define ND 1024
#define NH 64
#define SPL 2

typedef unsigned long long ull;

__device__ __forceinline__ uint32_t f2tf32(float f) {
    uint32_t u; asm("cvt.rna.tf32.f32 %0, %1;" : "=r"(u) : "f"(f)); return u;
}
__device__ __forceinline__ float tf32f(float f) {
    return __uint_as_float(f2tf32(f));
}

#define MMA_TF32(D, A0, A1, A2, A3, B0, B1)                                   \
    asm volatile(                                                             \
        "mma.sync.aligned.m16n8k8.row.col.f32.tf32.tf32.f32 "                 \
        "{%0,%1,%2,%3}, {%4,%5,%6,%7}, {%8,%9}, {%0,%1,%2,%3};"               \
        : "+f"((D)[0]), "+f"((D)[1]), "+f"((D)[2]), "+f"((D)[3])              \
        : "r"(A0), "r"(A1), "r"(A2), "r"(A3), "r"(B0), "r"(B1))

// Q,K,V row-major [b][t][h]; split-K partials.
__device__ float g_q [NB * NT * NH];
__device__ float g_k [NB * NT * NH];
__device__ float g_v [NB * NT * NH];
__device__ float g_po[(size_t)NB * NT * SPL * NH];
__device__ float g_pm[NB * NT * SPL];
__device__ float g_pl[NB * NT * SPL];

// ---------------------------------------------------------------------------
// Projection via mma.sync tf32. 256 thr / 8 warps, tile 64 x 192 (q|k|v),
// warp tile 32x48, BK=32 double-buffered. All outputs row-major.
// ---------------------------------------------------------------------------
#define PJ_AS 2304                 // 64*36
#define PJ_BS 6272                 // 32*196
#define PJ_BUF (PJ_AS + PJ_BS)
#define PJ_SMEM_BYTES (2 * PJ_BUF * 4)

__global__ __launch_bounds__(256) void proj_mma(
    const float* __restrict__ x, const float* __restrict__ Wq,
    const float* __restrict__ Wk, const float* __restrict__ Wv,
    const int* __restrict__ valid_lens)
{
    extern __shared__ float pjs[];
    const int b  = blockIdx.y;
    const int t0 = blockIdx.x * 64;
    int L = valid_lens[b];
    if (L < 0) L = 0;
    if (L > NT) L = NT;
    if (t0 >= L) return;

    const int tid  = threadIdx.x;
    const int lane = tid & 31;
    const int wid  = tid >> 5;
    const int g    = lane >> 2;
    const int t    = lane & 3;
    const int mrow = (wid & 1) * 32;
    const int ncol = (wid >> 1) * 48;

    const float* Wm[3] = { Wq, Wk, Wv };
    const int ar  = tid >> 3;
    const int ak4 = (tid & 7) * 4;

    float d[2][6][4];
    #pragma unroll
    for (int mt = 0; mt < 2; mt++)
        #pragma unroll
        for (int nt = 0; nt < 6; nt++)
            #pragma unroll
            for (int e = 0; e < 4; e++) d[mt][nt][e] = 0.f;

    {
        float* As = pjs;
        float* Bs = pjs + PJ_AS;
        #pragma unroll
        for (int i = 0; i < 2; i++) {
            int r = ar + 32 * i;
            float4 v = *(const float4*)&x[((size_t)b * NT + t0 + r) * ND + ak4];
            As[r * 36 + ak4 + 0] = tf32f(v.x);
            As[r * 36 + ak4 + 1] = tf32f(v.y);
            As[r * 36 + ak4 + 2] = tf32f(v.z);
            As[r * 36 + ak4 + 3] = tf32f(v.w);
        }
        #pragma unroll
        for (int i = 0; i < 6; i++) {
            int idx = tid + 256 * i;
            int k   = idx / 48;
            int c4  = (idx % 48) * 4;
            int j   = c4 >> 6;
            int hh  = c4 & 63;
            float4 v = *(const float4*)&Wm[j][(size_t)k * NH + hh];
            Bs[k * 196 + c4 + 0] = tf32f(v.x);
            Bs[k * 196 + c4 + 1] = tf32f(v.y);
            Bs[k * 196 + c4 + 2] = tf32f(v.z);
            Bs[k * 196 + c4 + 3] = tf32f(v.w);
        }
    }
    __syncthreads();

    int buf = 0;
    for (int c = 0; c < 32; c++) {
        const int kb = c * 32;
        const bool has_next = (c < 31);
        float4 pa[2], pb[6];
        if (has_next) {
            #pragma unroll
            for (int i = 0; i < 2; i++) {
                int r = ar + 32 * i;
                pa[i] = *(const float4*)&x[((size_t)b * NT + t0 + r) * ND + kb + 32 + ak4];
            }
            #pragma unroll
            for (int i = 0; i < 6; i++) {
                int idx = tid + 256 * i;
                int k   = idx / 48;
                int c4  = (idx % 48) * 4;
                pb[i] = *(const float4*)&Wm[c4 >> 6][(size_t)(kb + 32 + k) * NH + (c4 & 63)];
            }
        }

        const float* As = pjs + buf * PJ_BUF;
        const float* Bs = As + PJ_AS;
        #pragma unroll
        for (int k8 = 0; k8 < 4; k8++) {
            const int kc = k8 * 8 + t;
            uint32_t afr[2][4];
            #pragma unroll
            for (int mt = 0; mt < 2; mt++) {
                const int r0 = mrow + mt * 16 + g;
                afr[mt][0] = __float_as_uint(As[r0 * 36 + kc]);
                afr[mt][1] = __float_as_uint(As[(r0 + 8) * 36 + kc]);
                afr[mt][2] = __float_as_uint(As[r0 * 36 + kc + 4]);
                afr[mt][3] = __float_as_uint(As[(r0 + 8) * 36 + kc + 4]);
            }
            #pragma unroll
            for (int nt = 0; nt < 6; nt++) {
                const int n = ncol + nt * 8 + g;
                uint32_t b0 = __float_as_uint(Bs[kc * 196 + n]);
                uint32_t b1 = __float_as_uint(Bs[(kc + 4) * 196 + n]);
                #pragma unroll
                for (int mt = 0; mt < 2; mt++)
                    MMA_TF32(d[mt][nt], afr[mt][0], afr[mt][1], afr[mt][2], afr[mt][3], b0, b1);
            }
        }

        if (has_next) {
            float* As2 = pjs + (buf ^ 1) * PJ_BUF;
            float* Bs2 = As2 + PJ_AS;
            #pragma unroll
            for (int i = 0; i < 2; i++) {
                int r = ar + 32 * i;
                As2[r * 36 + ak4 + 0] = tf32f(pa[i].x);
                As2[r * 36 + ak4 + 1] = tf32f(pa[i].y);
                As2[r * 36 + ak4 + 2] = tf32f(pa[i].z);
                As2[r * 36 + ak4 + 3] = tf32f(pa[i].w);
            }
            #pragma unroll
            for (int i = 0; i < 6; i++) {
                int idx = tid + 256 * i;
                int k   = idx / 48;
                int c4  = (idx % 48) * 4;
                Bs2[k * 196 + c4 + 0] = tf32f(pb[i].x);
                Bs2[k * 196 + c4 + 1] = tf32f(pb[i].y);
                Bs2[k * 196 + c4 + 2] = tf32f(pb[i].z);
                Bs2[k * 196 + c4 + 3] = tf32f(pb[i].w);
            }
        }
        __syncthreads();
        buf ^= 1;
    }

    // epilogue: stage row-major [64][196], then coalesced row-major stores
    float* sm2 = pjs;
    #pragma unroll
    for (int mt = 0; mt < 2; mt++)
        #pragma unroll
        for (int nt = 0; nt < 6; nt++)
            #pragma unroll
            for (int e = 0; e < 4; e++) {
                const int r  = mrow + mt * 16 + g + ((e >= 2) ? 8 : 0);
                const int cc = ncol + nt * 8 + 2 * t + (e & 1);
                sm2[r * 196 + cc] = d[mt][nt][e];
            }
    __syncthreads();

    #pragma unroll
    for (int i = 0; i < 12; i++) {
        int idx = tid + 256 * i;          // 0..3071
        int r   = idx / 48;
        int c4  = (idx % 48) * 4;
        float4 v = *(const float4*)&sm2[r * 196 + c4];
        float* __restrict__ O = (c4 < 64) ? g_q : ((c4 < 128) ? g_k : g_v);
        *(float4*)&O[((size_t)b * NT + t0 + r) * NH + (c4 & 63)] = v;
    }
}

// ---------------------------------------------------------------------------
// Tensor-core flash attention partials. BQ=128, BK=64, 256 thr / 8 warps.
// Warp w owns rows w*16..w*16+15 and ALL 64 keys -> warp-local softmax.
// S: mma tf32 (Q frags in regs). P -> smem (overlays Q). PV: mma tf32.
// ---------------------------------------------------------------------------
#define BQ 128
#define AT_QP 0                       // QP [128][68]  (Q, then P)
#define AT_KS (128 * 68)              // Ks [64][68]
#define AT_VS (AT_KS + 64 * 68)       // Vs [64][68]
#define AT_FLOATS (AT_VS + 64 * 68)   // 17408 floats = 69632 B
#define AT_BYTES (AT_FLOATS * 4)

__global__ __launch_bounds__(256, 2) void attn_part(const int* __restrict__ valid_lens)
{
    extern __shared__ float sm[];
    const int b  = blockIdx.y;
    const int q0 = blockIdx.x * BQ;
    const int s  = blockIdx.z;
    int L = valid_lens[b];
    if (L < 0) L = 0;
    if (L > NT) L = NT;
    if (q0 >= L) return;

    const int tid  = threadIdx.x;
    const int lane = tid & 31;
    const int w    = tid >> 5;
    const int g    = lane >> 2;
    const int t    = lane & 3;
    const int r0   = w * 16 + g;     // tile row for d0/d1; r0+8 for d2/d3

    const int kend = (q0 + BQ < L) ? (q0 + BQ) : L;
    const int C  = (((kend + SPL - 1) / SPL) + 63) & ~63;
    const int jb = s * C;
    const int je = (jb + C < kend) ? (jb + C) : kend;

    if (jb >= je) {
        const float4 z4 = make_float4(0.f, 0.f, 0.f, 0.f);
        #pragma unroll
        for (int i = 0; i < 8; i++) {
            int idx = tid + 256 * i;
            int row = idx >> 4, h4 = (idx & 15) * 4;
            *(float4*)&g_po[((size_t)(b * NT + q0 + row) * SPL + s) * NH + h4] = z4;
        }
        if (tid < BQ) {
            g_pm[(size_t)(b * NT + q0 + tid) * SPL + s] = -1e30f;
            g_pl[(size_t)(b * NT + q0 + tid) * SPL + s] = 0.f;
        }
        return;
    }

    // load Q tile (128 x 64) as tf32
    #pragma unroll
    for (int i = 0; i < 8; i++) {
        int idx = tid + 256 * i;
        int r = idx >> 4, c4 = (idx & 15) * 4;
        float4 v = *(const float4*)&g_q[((size_t)b * NT + q0 + r) * NH + c4];
        sm[AT_QP + r * 68 + c4 + 0] = tf32f(v.x);
        sm[AT_QP + r * 68 + c4 + 1] = tf32f(v.y);
        sm[AT_QP + r * 68 + c4 + 2] = tf32f(v.z);
        sm[AT_QP + r * 68 + c4 + 3] = tf32f(v.w);
    }
    __syncthreads();

    // Q fragments (all 8 k-steps) into registers
    uint32_t qf[8][4];
    #pragma unroll
    for (int kc = 0; kc < 8; kc++) {
        const int k0 = kc * 8;
        qf[kc][0] = __float_as_uint(sm[AT_QP + r0 * 68 + k0 + t]);
        qf[kc][1] = __float_as_uint(sm[AT_QP + (r0 + 8) * 68 + k0 + t]);
        qf[kc][2] = __float_as_uint(sm[AT_QP + r0 * 68 + k0 + t + 4]);
        qf[kc][3] = __float_as_uint(sm[AT_QP + (r0 + 8) * 68 + k0 + t + 4]);
    }
    __syncthreads();   // everyone done reading Q before P overwrites (paranoia)

    float m0 = -1e30f, m1 = -1e30f, l0 = 0.f, l1 = 0.f;
    float o[8][4];
    #pragma unroll
    for (int nt = 0; nt < 8; nt++)
        #pragma unroll
        for (int e = 0; e < 4; e++) o[nt][e] = 0.f;

    for (int j0 = jb; j0 < je; j0 += 64) {
        __syncthreads();
        // K,V tiles 64x64 as tf32
        #pragma unroll
        for (int i = 0; i < 4; i++) {
            int idx = tid + 256 * i;
            int r = idx >> 4, c4 = (idx & 15) * 4;
            float4 kv = *(const float4*)&g_k[((size_t)b * NT + j0 + r) * NH + c4];
            float4 vv = *(const float4*)&g_v[((size_t)b * NT + j0 + r) * NH + c4];
            sm[AT_KS + r * 68 + c4 + 0] = tf32f(kv.x);
            sm[AT_KS + r * 68 + c4 + 1] = tf32f(kv.y);
            sm[AT_KS + r * 68 + c4 + 2] = tf32f(kv.z);
            sm[AT_KS + r * 68 + c4 + 3] = tf32f(kv.w);
            sm[AT_VS + r * 68 + c4 + 0] = tf32f(vv.x);
            sm[AT_VS + r * 68 + c4 + 1] = tf32f(vv.y);
            sm[AT_VS + r * 68 + c4 + 2] = tf32f(vv.z);
            sm[AT_VS + r * 68 + c4 + 3] = tf32f(vv.w);
        }
        __syncthreads();

        // ---- S = Q K^T  (warp rows x 64 keys)
        float sv[8][4];
        #pragma unroll
        for (int nt = 0; nt < 8; nt++)
            #pragma unroll
            for (int e = 0; e < 4; e++) sv[nt][e] = 0.f;

        #pragma unroll
        for (int kc = 0; kc < 8; kc++) {
            const int k0 = kc * 8;
            #pragma unroll
            for (int nt = 0; nt < 8; nt++) {
                const int n = nt * 8 + g;
                uint32_t b0 = __float_as_uint(sm[AT_KS + n * 68 + k0 + t]);
                uint32_t b1 = __float_as_uint(sm[AT_KS + n * 68 + k0 + t + 4]);
                MMA_TF32(sv[nt], qf[kc][0], qf[kc][1], qf[kc][2], qf[kc][3], b0, b1);
            }
        }

        // ---- mask + scale
        const int qg0 = q0 + r0;
        const int qg1 = qg0 + 8;
        #pragma unroll
        for (int nt = 0; nt < 8; nt++) {
            #pragma unroll
            for (int e = 0; e < 4; e++) {
                const int key = j0 + nt * 8 + 2 * t + (e & 1);
                const int q   = (e & 2) ? qg1 : qg0;
                const bool valid = (key <= q) && (key < L);
                sv[nt][e] = valid ? sv[nt][e] * 0.125f : -1e30f;
            }
        }

        // ---- warp-local softmax (quad reduce)
        float tm0 = -1e30f, tm1 = -1e30f;
        #pragma unroll
        for (int nt = 0; nt < 8; nt++) {
            tm0 = fmaxf(tm0, fmaxf(sv[nt][0], sv[nt][1]));
            tm1 = fmaxf(tm1, fmaxf(sv[nt][2], sv[nt][3]));
        }
        #pragma unroll
        for (int off = 1; off < 4; off <<= 1) {
            tm0 = fmaxf(tm0, __shfl_xor_sync(0xffffffffu, tm0, off));
            tm1 = fmaxf(tm1, __shfl_xor_sync(0xffffffffu, tm1, off));
        }
        const float mn0 = fmaxf(m0, tm0), mn1 = fmaxf(m1, tm1);
        const float corr0 = __expf(m0 - mn0), corr1 = __expf(m1 - mn1);

        float ps0 = 0.f, ps1 = 0.f;
        float pv[8][4];
        #pragma unroll
        for (int nt = 0; nt < 8; nt++) {
            pv[nt][0] = (sv[nt][0] > -1e29f) ? __expf(sv[nt][0] - mn0) : 0.f;
            pv[nt][1] = (sv[nt][1] > -1e29f) ? __expf(sv[nt][1] - mn0) : 0.f;
            pv[nt][2] = (sv[nt][2] > -1e29f) ? __expf(sv[nt][2] - mn1) : 0.f;
            pv[nt][3] = (sv[nt][3] > -1e29f) ? __expf(sv[nt][3] - mn1) : 0.f;
            ps0 += pv[nt][0] + pv[nt][1];
            ps1 += pv[nt][2] + pv[nt][3];
        }
        #pragma unroll
        for (int off = 1; off < 4; off <<= 1) {
            ps0 += __shfl_xor_sync(0xffffffffu, ps0, off);
            ps1 += __shfl_xor_sync(0xffffffffu, ps1, off);
        }
        l0 = l0 * corr0 + ps0; m0 = mn0;
        l1 = l1 * corr1 + ps1; m1 = mn1;

        // rescale O, store P (tf32) to warp-local smem rows
        #pragma unroll
        for (int nt = 0; nt < 8; nt++) {
            o[nt][0] *= corr0; o[nt][1] *= corr0;
            o[nt][2] *= corr1; o[nt][3] *= corr1;
            const int cc = nt * 8 + 2 * t;
            sm[AT_QP + r0 * 68 + cc]           = tf32f(pv[nt][0]);
            sm[AT_QP + r0 * 68 + cc + 1]       = tf32f(pv[nt][1]);
            sm[AT_QP + (r0 + 8) * 68 + cc]     = tf32f(pv[nt][2]);
            sm[AT_QP + (r0 + 8) * 68 + cc + 1] = tf32f(pv[nt][3]);
        }
        __syncwarp();

        // ---- O += P V
        #pragma unroll
        for (int kc = 0; kc < 8; kc++) {
            const int k0 = kc * 8;
            uint32_t a0 = __float_as_uint(sm[AT_QP + r0 * 68 + k0 + t]);
            uint32_t a1 = __float_as_uint(sm[AT_QP + (r0 + 8) * 68 + k0 + t]);
            uint32_t a2 = __float_as_uint(sm[AT_QP + r0 * 68 + k0 + t + 4]);
            uint32_t a3 = __float_as_uint(sm[AT_QP + (r0 + 8) * 68 + k0 + t + 4]);
            #pragma unroll
            for (int nt = 0; nt < 8; nt++) {
                const int n = nt * 8 + g;
                uint32_t b0 = __float_as_uint(sm[AT_VS + (k0 + t) * 68 + n]);
                uint32_t b1 = __float_as_uint(sm[AT_VS + (k0 + t + 4) * 68 + n]);
                MMA_TF32(o[nt], a0, a1, a2, a3, b0, b1);
            }
        }
        __syncwarp();
    }

    // write partials
    const size_t pr0 = ((size_t)(b * NT + q0 + r0) * SPL + s);
    const size_t pr1 = ((size_t)(b * NT + q0 + r0 + 8) * SPL + s);
    #pragma unroll
    for (int nt = 0; nt < 8; nt++) {
        const int cc = nt * 8 + 2 * t;
        *(float2*)&g_po[pr0 * NH + cc] = make_float2(o[nt][0], o[nt][1]);
        *(float2*)&g_po[pr1 * NH + cc] = make_float2(o[nt][2], o[nt][3]);
    }
    if (t == 0) {
        g_pm[pr0] = m0; g_pl[pr0] = l0;
        g_pm[pr1] = m1; g_pl[pr1] = l1;
    }
}

// ---------------------------------------------------------------------------
// Combine split-K partials.
// ---------------------------------------------------------------------------
__global__ __launch_bounds__(128) void attn_combine(
    const int* __restrict__ valid_lens, float* __restrict__ out)
{
    const int b   = blockIdx.y;
    const int tid = threadIdx.x;
    const int row = tid >> 3;
    const int t8  = tid & 7;
    const int q   = blockIdx.x * 16 + row;
    int L = valid_lens[b];
    if (L < 0) L = 0;
    if (L > NT) L = NT;

    const size_t base0 = (size_t)(b * NT + q) * SPL;
    float ms[SPL], mstar = -1e30f;
    #pragma unroll
    for (int s = 0; s < SPL; s++) {
        ms[s] = g_pm[base0 + s];
        mstar = fmaxf(mstar, ms[s]);
    }
    float l = 0.f;
    float4 oA = make_float4(0.f, 0.f, 0.f, 0.f);
    float4 oB = make_float4(0.f, 0.f, 0.f, 0.f);
    #pragma unroll
    for (int s = 0; s < SPL; s++) {
        const float w = (ms[s] > -1e29f) ? __expf(ms[s] - mstar) : 0.f;
        l += g_pl[base0 + s] * w;
        float4 a = *(const float4*)&g_po[(base0 + s) * NH + t8 * 4];
        float4 c = *(const float4*)&g_po[(base0 + s) * NH + 32 + t8 * 4];
        oA.x += a.x * w; oA.y += a.y * w; oA.z += a.z * w; oA.w += a.w * w;
        oB.x += c.x * w; oB.y += c.y * w; oB.z += c.z * w; oB.w += c.w * w;
    }
    const float inv = (q < L && l > 0.f) ? (1.f / l) : 0.f;
    const size_t ob = ((size_t)b * NT + q) * NH;
    *(float4*)&out[ob + t8 * 4] =
        make_float4(oA.x * inv, oA.y * inv, oA.z * inv, oA.w * inv);
    *(float4*)&out[ob + 32 + t8 * 4] =
        make_float4(oB.x * inv, oB.y * inv, oB.z * inv, oB.w * inv);
}

extern "C" void kernel_launch(void* const* d_in, const int* in_sizes, int n_in,
                              void* d_out, int out_size)
{
    const float* x  = (const float*)d_in[0];
    const float* Wq = (const float*)d_in[1];
    const float* Wk = (const float*)d_in[2];
    const float* Wv = (const float*)d_in[3];
    const int*   vl = (const int*)d_in[4];
    float* out = (float*)d_out;

    cudaFuncSetAttribute(proj_mma, cudaFuncAttributeMaxDynamicSharedMemorySize, PJ_SMEM_BYTES);
    cudaFuncSetAttribute(attn_part, cudaFuncAttributeMaxDynamicSharedMemorySize, AT_BYTES);

    proj_mma<<<dim3(NT / 64, NB), 256, PJ_SMEM_BYTES>>>(x, Wq, Wk, Wv, vl);
    attn_part<<<dim3(NT / BQ, NB, SPL), 256, AT_BYTES>>>(vl);
    attn_combine<<<dim3(NT / 16, NB), 128>>>(vl, out);
}

// round 13
// speedup vs baseline: 3.2396x; 1.2471x over previous
#include <cuda_runtime.h>
#include <cstdint>

#define NB 8
#define NT 2048
#define ND 1024
#define NH 64
#define SPL 4

typedef unsigned long long ull;

__device__ __forceinline__ uint32_t f2tf32(float f) {
    uint32_t u; asm("cvt.rna.tf32.f32 %0, %1;" : "=r"(u) : "f"(f)); return u;
}
__device__ __forceinline__ float tf32f(float f) {
    return __uint_as_float(f2tf32(f));
}

#define MMA_TF32(D, A0, A1, A2, A3, B0, B1)                                   \
    asm volatile(                                                             \
        "mma.sync.aligned.m16n8k8.row.col.f32.tf32.tf32.f32 "                 \
        "{%0,%1,%2,%3}, {%4,%5,%6,%7}, {%8,%9}, {%0,%1,%2,%3};"               \
        : "+f"((D)[0]), "+f"((D)[1]), "+f"((D)[2]), "+f"((D)[3])              \
        : "r"(A0), "r"(A1), "r"(A2), "r"(A3), "r"(B0), "r"(B1))

// Q,K,V row-major [b][t][h]; split-K partials.
__device__ float g_q [NB * NT * NH];
__device__ float g_k [NB * NT * NH];
__device__ float g_v [NB * NT * NH];
__device__ float g_po[(size_t)NB * NT * SPL * NH];
__device__ float g_pm[NB * NT * SPL];
__device__ float g_pl[NB * NT * SPL];

// ---------------------------------------------------------------------------
// Projection via mma.sync tf32. Tile 32 rows x 96 cols (z = column half of
// q|k|v). 256 thr / 8 warps (2 row-groups x 4 col-groups), warp tile 16x24.
// BK=32 double-buffered, register-staged prefetch. Strides: A 40, B 104
// (conflict-free fragment LDS: banks 8g+t / 8t+g).
// ---------------------------------------------------------------------------
#define PJ_ASTR 40
#define PJ_BSTR 104
#define PJ_AS (32 * PJ_ASTR)
#define PJ_BS (32 * PJ_BSTR)
#define PJ_BUF (PJ_AS + PJ_BS)
#define PJ_SMEM_BYTES (2 * PJ_BUF * 4)   // 36864 B

__global__ __launch_bounds__(256) void proj_mma(
    const float* __restrict__ x, const float* __restrict__ Wq,
    const float* __restrict__ Wk, const float* __restrict__ Wv,
    const int* __restrict__ valid_lens)
{
    extern __shared__ float pjs[];
    const int b    = blockIdx.y;
    const int t0   = blockIdx.x * 32;
    const int half = blockIdx.z;           // 0: cols 0..95, 1: cols 96..191
    int L = valid_lens[b];
    if (L < 0) L = 0;
    if (L > NT) L = NT;
    if (t0 >= L) return;

    const int tid  = threadIdx.x;
    const int lane = tid & 31;
    const int wid  = tid >> 5;
    const int g    = lane >> 2;
    const int t    = lane & 3;
    const int row0 = (wid & 1) * 16 + g;
    const int col0 = (wid >> 1) * 24;

    const float* Wm[3] = { Wq, Wk, Wv };
    const int ar  = tid >> 3;             // A row 0..31
    const int ak4 = (tid & 7) * 4;        // A k 0..28

    float d[3][4];
    #pragma unroll
    for (int nt = 0; nt < 3; nt++)
        #pragma unroll
        for (int e = 0; e < 4; e++) d[nt][e] = 0.f;

    // preload chunk 0
    {
        float* As = pjs;
        float* Bs = pjs + PJ_AS;
        float4 v = *(const float4*)&x[((size_t)b * NT + t0 + ar) * ND + ak4];
        As[ar * PJ_ASTR + ak4 + 0] = tf32f(v.x);
        As[ar * PJ_ASTR + ak4 + 1] = tf32f(v.y);
        As[ar * PJ_ASTR + ak4 + 2] = tf32f(v.z);
        As[ar * PJ_ASTR + ak4 + 3] = tf32f(v.w);
        #pragma unroll
        for (int i = 0; i < 3; i++) {
            int idx = tid + 256 * i;       // 0..767
            int k   = idx / 24;
            int c4  = (idx % 24) * 4;
            int gc  = half * 96 + c4;
            float4 w = *(const float4*)&Wm[gc >> 6][(size_t)k * NH + (gc & 63)];
            Bs[k * PJ_BSTR + c4 + 0] = tf32f(w.x);
            Bs[k * PJ_BSTR + c4 + 1] = tf32f(w.y);
            Bs[k * PJ_BSTR + c4 + 2] = tf32f(w.z);
            Bs[k * PJ_BSTR + c4 + 3] = tf32f(w.w);
        }
    }
    __syncthreads();

    int buf = 0;
    for (int c = 0; c < 32; c++) {
        const int kb = c * 32;
        const bool has_next = (c < 31);
        float4 pa, pb[3];
        if (has_next) {
            pa = *(const float4*)&x[((size_t)b * NT + t0 + ar) * ND + kb + 32 + ak4];
            #pragma unroll
            for (int i = 0; i < 3; i++) {
                int idx = tid + 256 * i;
                int k   = idx / 24;
                int c4  = (idx % 24) * 4;
                int gc  = half * 96 + c4;
                pb[i] = *(const float4*)&Wm[gc >> 6][(size_t)(kb + 32 + k) * NH + (gc & 63)];
            }
        }

        const float* As = pjs + buf * PJ_BUF;
        const float* Bs = As + PJ_AS;
        #pragma unroll
        for (int k8 = 0; k8 < 4; k8++) {
            const int kc = k8 * 8 + t;
            uint32_t a0 = __float_as_uint(As[row0 * PJ_ASTR + kc]);
            uint32_t a1 = __float_as_uint(As[(row0 + 8) * PJ_ASTR + kc]);
            uint32_t a2 = __float_as_uint(As[row0 * PJ_ASTR + kc + 4]);
            uint32_t a3 = __float_as_uint(As[(row0 + 8) * PJ_ASTR + kc + 4]);
            #pragma unroll
            for (int nt = 0; nt < 3; nt++) {
                const int n = col0 + nt * 8 + g;
                uint32_t b0 = __float_as_uint(Bs[kc * PJ_BSTR + n]);
                uint32_t b1 = __float_as_uint(Bs[(kc + 4) * PJ_BSTR + n]);
                MMA_TF32(d[nt], a0, a1, a2, a3, b0, b1);
            }
        }

        if (has_next) {
            float* As2 = pjs + (buf ^ 1) * PJ_BUF;
            float* Bs2 = As2 + PJ_AS;
            As2[ar * PJ_ASTR + ak4 + 0] = tf32f(pa.x);
            As2[ar * PJ_ASTR + ak4 + 1] = tf32f(pa.y);
            As2[ar * PJ_ASTR + ak4 + 2] = tf32f(pa.z);
            As2[ar * PJ_ASTR + ak4 + 3] = tf32f(pa.w);
            #pragma unroll
            for (int i = 0; i < 3; i++) {
                int idx = tid + 256 * i;
                int k   = idx / 24;
                int c4  = (idx % 24) * 4;
                Bs2[k * PJ_BSTR + c4 + 0] = tf32f(pb[i].x);
                Bs2[k * PJ_BSTR + c4 + 1] = tf32f(pb[i].y);
                Bs2[k * PJ_BSTR + c4 + 2] = tf32f(pb[i].z);
                Bs2[k * PJ_BSTR + c4 + 3] = tf32f(pb[i].w);
            }
        }
        __syncthreads();
        buf ^= 1;
    }

    // epilogue: stage [32][100], coalesced stores
    float* sm2 = pjs;
    #pragma unroll
    for (int nt = 0; nt < 3; nt++)
        #pragma unroll
        for (int e = 0; e < 4; e++) {
            const int r  = row0 + ((e >= 2) ? 8 : 0);
            const int cc = col0 + nt * 8 + 2 * t + (e & 1);
            sm2[r * 100 + cc] = d[nt][e];
        }
    __syncthreads();

    #pragma unroll
    for (int i = 0; i < 3; i++) {
        int idx = tid + 256 * i;          // 0..767
        int r   = idx / 24;
        int c4  = (idx % 24) * 4;
        float4 v = *(const float4*)&sm2[r * 100 + c4];
        int gc = half * 96 + c4;
        float* __restrict__ O = (gc < 64) ? g_q : ((gc < 128) ? g_k : g_v);
        *(float4*)&O[((size_t)b * NT + t0 + r) * NH + (gc & 63)] = v;
    }
}

// ---------------------------------------------------------------------------
// Tensor-core flash attention partials. BQ=128, BK=64, 256 thr / 8 warps,
// SPL=4 split-K. (same structure as round 12)
// ---------------------------------------------------------------------------
#define BQ 128
#define AT_QP 0
#define AT_KS (128 * 68)
#define AT_VS (AT_KS + 64 * 68)
#define AT_FLOATS (AT_VS + 64 * 68)
#define AT_BYTES (AT_FLOATS * 4)

__global__ __launch_bounds__(256, 2) void attn_part(const int* __restrict__ valid_lens)
{
    extern __shared__ float sm[];
    const int b  = blockIdx.y;
    const int q0 = blockIdx.x * BQ;
    const int s  = blockIdx.z;
    int L = valid_lens[b];
    if (L < 0) L = 0;
    if (L > NT) L = NT;
    if (q0 >= L) return;

    const int tid  = threadIdx.x;
    const int lane = tid & 31;
    const int w    = tid >> 5;
    const int g    = lane >> 2;
    const int t    = lane & 3;
    const int r0   = w * 16 + g;

    const int kend = (q0 + BQ < L) ? (q0 + BQ) : L;
    const int C  = (((kend + SPL - 1) / SPL) + 63) & ~63;
    const int jb = s * C;
    const int je = (jb + C < kend) ? (jb + C) : kend;

    if (jb >= je) {
        const float4 z4 = make_float4(0.f, 0.f, 0.f, 0.f);
        #pragma unroll
        for (int i = 0; i < 8; i++) {
            int idx = tid + 256 * i;
            int row = idx >> 4, h4 = (idx & 15) * 4;
            *(float4*)&g_po[((size_t)(b * NT + q0 + row) * SPL + s) * NH + h4] = z4;
        }
        if (tid < BQ) {
            g_pm[(size_t)(b * NT + q0 + tid) * SPL + s] = -1e30f;
            g_pl[(size_t)(b * NT + q0 + tid) * SPL + s] = 0.f;
        }
        return;
    }

    #pragma unroll
    for (int i = 0; i < 8; i++) {
        int idx = tid + 256 * i;
        int r = idx >> 4, c4 = (idx & 15) * 4;
        float4 v = *(const float4*)&g_q[((size_t)b * NT + q0 + r) * NH + c4];
        sm[AT_QP + r * 68 + c4 + 0] = tf32f(v.x);
        sm[AT_QP + r * 68 + c4 + 1] = tf32f(v.y);
        sm[AT_QP + r * 68 + c4 + 2] = tf32f(v.z);
        sm[AT_QP + r * 68 + c4 + 3] = tf32f(v.w);
    }
    __syncthreads();

    uint32_t qf[8][4];
    #pragma unroll
    for (int kc = 0; kc < 8; kc++) {
        const int k0 = kc * 8;
        qf[kc][0] = __float_as_uint(sm[AT_QP + r0 * 68 + k0 + t]);
        qf[kc][1] = __float_as_uint(sm[AT_QP + (r0 + 8) * 68 + k0 + t]);
        qf[kc][2] = __float_as_uint(sm[AT_QP + r0 * 68 + k0 + t + 4]);
        qf[kc][3] = __float_as_uint(sm[AT_QP + (r0 + 8) * 68 + k0 + t + 4]);
    }
    __syncthreads();

    float m0 = -1e30f, m1 = -1e30f, l0 = 0.f, l1 = 0.f;
    float o[8][4];
    #pragma unroll
    for (int nt = 0; nt < 8; nt++)
        #pragma unroll
        for (int e = 0; e < 4; e++) o[nt][e] = 0.f;

    for (int j0 = jb; j0 < je; j0 += 64) {
        __syncthreads();
        #pragma unroll
        for (int i = 0; i < 4; i++) {
            int idx = tid + 256 * i;
            int r = idx >> 4, c4 = (idx & 15) * 4;
            float4 kv = *(const float4*)&g_k[((size_t)b * NT + j0 + r) * NH + c4];
            float4 vv = *(const float4*)&g_v[((size_t)b * NT + j0 + r) * NH + c4];
            sm[AT_KS + r * 68 + c4 + 0] = tf32f(kv.x);
            sm[AT_KS + r * 68 + c4 + 1] = tf32f(kv.y);
            sm[AT_KS + r * 68 + c4 + 2] = tf32f(kv.z);
            sm[AT_KS + r * 68 + c4 + 3] = tf32f(kv.w);
            sm[AT_VS + r * 68 + c4 + 0] = tf32f(vv.x);
            sm[AT_VS + r * 68 + c4 + 1] = tf32f(vv.y);
            sm[AT_VS + r * 68 + c4 + 2] = tf32f(vv.z);
            sm[AT_VS + r * 68 + c4 + 3] = tf32f(vv.w);
        }
        __syncthreads();

        float sv[8][4];
        #pragma unroll
        for (int nt = 0; nt < 8; nt++)
            #pragma unroll
            for (int e = 0; e < 4; e++) sv[nt][e] = 0.f;

        #pragma unroll
        for (int kc = 0; kc < 8; kc++) {
            const int k0 = kc * 8;
            #pragma unroll
            for (int nt = 0; nt < 8; nt++) {
                const int n = nt * 8 + g;
                uint32_t b0 = __float_as_uint(sm[AT_KS + n * 68 + k0 + t]);
                uint32_t b1 = __float_as_uint(sm[AT_KS + n * 68 + k0 + t + 4]);
                MMA_TF32(sv[nt], qf[kc][0], qf[kc][1], qf[kc][2], qf[kc][3], b0, b1);
            }
        }

        const int qg0 = q0 + r0;
        const int qg1 = qg0 + 8;
        #pragma unroll
        for (int nt = 0; nt < 8; nt++) {
            #pragma unroll
            for (int e = 0; e < 4; e++) {
                const int key = j0 + nt * 8 + 2 * t + (e & 1);
                const int q   = (e & 2) ? qg1 : qg0;
                const bool valid = (key <= q) && (key < L);
                sv[nt][e] = valid ? sv[nt][e] * 0.125f : -1e30f;
            }
        }

        float tm0 = -1e30f, tm1 = -1e30f;
        #pragma unroll
        for (int nt = 0; nt < 8; nt++) {
            tm0 = fmaxf(tm0, fmaxf(sv[nt][0], sv[nt][1]));
            tm1 = fmaxf(tm1, fmaxf(sv[nt][2], sv[nt][3]));
        }
        #pragma unroll
        for (int off = 1; off < 4; off <<= 1) {
            tm0 = fmaxf(tm0, __shfl_xor_sync(0xffffffffu, tm0, off));
            tm1 = fmaxf(tm1, __shfl_xor_sync(0xffffffffu, tm1, off));
        }
        const float mn0 = fmaxf(m0, tm0), mn1 = fmaxf(m1, tm1);
        const float corr0 = __expf(m0 - mn0), corr1 = __expf(m1 - mn1);

        float ps0 = 0.f, ps1 = 0.f;
        float pv[8][4];
        #pragma unroll
        for (int nt = 0; nt < 8; nt++) {
            pv[nt][0] = (sv[nt][0] > -1e29f) ? __expf(sv[nt][0] - mn0) : 0.f;
            pv[nt][1] = (sv[nt][1] > -1e29f) ? __expf(sv[nt][1] - mn0) : 0.f;
            pv[nt][2] = (sv[nt][2] > -1e29f) ? __expf(sv[nt][2] - mn1) : 0.f;
            pv[nt][3] = (sv[nt][3] > -1e29f) ? __expf(sv[nt][3] - mn1) : 0.f;
            ps0 += pv[nt][0] + pv[nt][1];
            ps1 += pv[nt][2] + pv[nt][3];
        }
        #pragma unroll
        for (int off = 1; off < 4; off <<= 1) {
            ps0 += __shfl_xor_sync(0xffffffffu, ps0, off);
            ps1 += __shfl_xor_sync(0xffffffffu, ps1, off);
        }
        l0 = l0 * corr0 + ps0; m0 = mn0;
        l1 = l1 * corr1 + ps1; m1 = mn1;

        #pragma unroll
        for (int nt = 0; nt < 8; nt++) {
            o[nt][0] *= corr0; o[nt][1] *= corr0;
            o[nt][2] *= corr1; o[nt][3] *= corr1;
            const int cc = nt * 8 + 2 * t;
            sm[AT_QP + r0 * 68 + cc]           = tf32f(pv[nt][0]);
            sm[AT_QP + r0 * 68 + cc + 1]       = tf32f(pv[nt][1]);
            sm[AT_QP + (r0 + 8) * 68 + cc]     = tf32f(pv[nt][2]);
            sm[AT_QP + (r0 + 8) * 68 + cc + 1] = tf32f(pv[nt][3]);
        }
        __syncwarp();

        #pragma unroll
        for (int kc = 0; kc < 8; kc++) {
            const int k0 = kc * 8;
            uint32_t a0 = __float_as_uint(sm[AT_QP + r0 * 68 + k0 + t]);
            uint32_t a1 = __float_as_uint(sm[AT_QP + (r0 + 8) * 68 + k0 + t]);
            uint32_t a2 = __float_as_uint(sm[AT_QP + r0 * 68 + k0 + t + 4]);
            uint32_t a3 = __float_as_uint(sm[AT_QP + (r0 + 8) * 68 + k0 + t + 4]);
            #pragma unroll
            for (int nt = 0; nt < 8; nt++) {
                const int n = nt * 8 + g;
                uint32_t b0 = __float_as_uint(sm[AT_VS + (k0 + t) * 68 + n]);
                uint32_t b1 = __float_as_uint(sm[AT_VS + (k0 + t + 4) * 68 + n]);
                MMA_TF32(o[nt], a0, a1, a2, a3, b0, b1);
            }
        }
        __syncwarp();
    }

    const size_t pr0 = ((size_t)(b * NT + q0 + r0) * SPL + s);
    const size_t pr1 = ((size_t)(b * NT + q0 + r0 + 8) * SPL + s);
    #pragma unroll
    for (int nt = 0; nt < 8; nt++) {
        const int cc = nt * 8 + 2 * t;
        *(float2*)&g_po[pr0 * NH + cc] = make_float2(o[nt][0], o[nt][1]);
        *(float2*)&g_po[pr1 * NH + cc] = make_float2(o[nt][2], o[nt][3]);
    }
    if (t == 0) {
        g_pm[pr0] = m0; g_pl[pr0] = l0;
        g_pm[pr1] = m1; g_pl[pr1] = l1;
    }
}

// ---------------------------------------------------------------------------
// Combine split-K partials.
// ---------------------------------------------------------------------------
__global__ __launch_bounds__(128) void attn_combine(
    const int* __restrict__ valid_lens, float* __restrict__ out)
{
    const int b   = blockIdx.y;
    const int tid = threadIdx.x;
    const int row = tid >> 3;
    const int t8  = tid & 7;
    const int q   = blockIdx.x * 16 + row;
    int L = valid_lens[b];
    if (L < 0) L = 0;
    if (L > NT) L = NT;

    const size_t base0 = (size_t)(b * NT + q) * SPL;
    float ms[SPL], mstar = -1e30f;
    #pragma unroll
    for (int s = 0; s < SPL; s++) {
        ms[s] = g_pm[base0 + s];
        mstar = fmaxf(mstar, ms[s]);
    }
    float l = 0.f;
    float4 oA = make_float4(0.f, 0.f, 0.f, 0.f);
    float4 oB = make_float4(0.f, 0.f, 0.f, 0.f);
    #pragma unroll
    for (int s = 0; s < SPL; s++) {
        const float w = (ms[s] > -1e29f) ? __expf(ms[s] - mstar) : 0.f;
        l += g_pl[base0 + s] * w;
        float4 a = *(const float4*)&g_po[(base0 + s) * NH + t8 * 4];
        float4 c = *(const float4*)&g_po[(base0 + s) * NH + 32 + t8 * 4];
        oA.x += a.x * w; oA.y += a.y * w; oA.z += a.z * w; oA.w += a.w * w;
        oB.x += c.x * w; oB.y += c.y * w; oB.z += c.z * w; oB.w += c.w * w;
    }
    const float inv = (q < L && l > 0.f) ? (1.f / l) : 0.f;
    const size_t ob = ((size_t)b * NT + q) * NH;
    *(float4*)&out[ob + t8 * 4] =
        make_float4(oA.x * inv, oA.y * inv, oA.z * inv, oA.w * inv);
    *(float4*)&out[ob + 32 + t8 * 4] =
        make_float4(oB.x * inv, oB.y * inv, oB.z * inv, oB.w * inv);
}

extern "C" void kernel_launch(void* const* d_in, const int* in_sizes, int n_in,
                              void* d_out, int out_size)
{
    const float* x  = (const float*)d_in[0];
    const float* Wq = (const float*)d_in[1];
    const float* Wk = (const float*)d_in[2];
    const float* Wv = (const float*)d_in[3];
    const int*   vl = (const int*)d_in[4];
    float* out = (float*)d_out;

    cudaFuncSetAttribute(proj_mma, cudaFuncAttributeMaxDynamicSharedMemorySize, PJ_SMEM_BYTES);
    cudaFuncSetAttribute(attn_part, cudaFuncAttributeMaxDynamicSharedMemorySize, AT_BYTES);

    proj_mma<<<dim3(NT / 32, NB, 2), 256, PJ_SMEM_BYTES>>>(x, Wq, Wk, Wv, vl);
    attn_part<<<dim3(NT / BQ, NB, SPL), 256, AT_BYTES>>>(vl);
    attn_combine<<<dim3(NT / 16, NB), 128>>>(vl, out);
}